// round 1
// baseline (speedup 1.0000x reference)
#include <cuda_runtime.h>

// Problem constants
#define BB 32
#define SS 4096
#define DD 64
#define KCC 256

// Scratch (device globals — no allocation allowed)
__device__ float g_Ke[BB * DD * KCC];   // [b][d][k]
__device__ float g_Vf[BB * KCC * DD];   // [b][k][d]

// ---------------------------------------------------------------------------
// Kernel A: projection GEMMs.
//   proj==0: g_Ke[b][d][k] = sum_s K[b][s][d] * E_w[k][s] + E_b[k]
//   proj==1: g_Vf[b][k][d] = sum_s V[b][s][d] * F_w[k][s] + F_b[k]
// Grid: (KC/32, B, 2). Block: 256 threads = (32 k-lanes) x (8 d-groups).
// Each thread: 1 k, 8 d outputs; reduction over S in chunks of 64.
// ---------------------------------------------------------------------------
__global__ __launch_bounds__(256) void proj_kernel(
    const float* __restrict__ K, const float* __restrict__ V,
    const float* __restrict__ E_w, const float* __restrict__ E_b,
    const float* __restrict__ F_w, const float* __restrict__ F_b)
{
    __shared__ float Xs[64][64];   // [s_local][d]
    __shared__ float Ws[32][65];   // [k_local][s_local], pad 65 -> conflict-free reads

    const int k0   = blockIdx.x * 32;
    const int b    = blockIdx.y;
    const int proj = blockIdx.z;

    const float* __restrict__ X    = proj ? V   : K;
    const float* __restrict__ W    = proj ? F_w : E_w;
    const float* __restrict__ bias = proj ? F_b : E_b;

    const int tid = threadIdx.x;
    const int x   = tid & 31;   // k lane
    const int y   = tid >> 5;   // d group

    float acc[8];
#pragma unroll
    for (int i = 0; i < 8; i++) acc[i] = 0.f;

    const float* Xb = X + (size_t)b * SS * DD;

    for (int s0 = 0; s0 < SS; s0 += 64) {
        // Load X tile: 64 rows x 64 d = 1024 float4, 4 per thread (coalesced)
#pragma unroll
        for (int t = tid; t < 64 * 16; t += 256) {
            int r = t >> 4, c = t & 15;
            reinterpret_cast<float4*>(Xs[r])[c] =
                reinterpret_cast<const float4*>(Xb + (size_t)(s0 + r) * DD)[c];
        }
        // Load W tile: 32 k-rows x 64 s = 512 float4, 2 per thread (coalesced)
#pragma unroll
        for (int t = tid; t < 32 * 16; t += 256) {
            int kr = t >> 4, c = t & 15;
            float4 v = reinterpret_cast<const float4*>(
                W + (size_t)(k0 + kr) * SS + s0)[c];
            Ws[kr][c * 4 + 0] = v.x;
            Ws[kr][c * 4 + 1] = v.y;
            Ws[kr][c * 4 + 2] = v.z;
            Ws[kr][c * 4 + 3] = v.w;
        }
        __syncthreads();

#pragma unroll 4
        for (int i = 0; i < 64; i++) {
            float w = Ws[x][i];   // bank (x+i)%32 -> conflict-free
            float4 xa = reinterpret_cast<const float4*>(Xs[i])[y * 2];     // broadcast
            float4 xb = reinterpret_cast<const float4*>(Xs[i])[y * 2 + 1]; // broadcast
            acc[0] += w * xa.x; acc[1] += w * xa.y;
            acc[2] += w * xa.z; acc[3] += w * xa.w;
            acc[4] += w * xb.x; acc[5] += w * xb.y;
            acc[6] += w * xb.z; acc[7] += w * xb.w;
        }
        __syncthreads();
    }

    const float bv = bias[k0 + x];
    if (proj == 0) {
        float* o = g_Ke + ((size_t)b * DD + y * 8) * KCC + k0 + x;
#pragma unroll
        for (int dd = 0; dd < 8; dd++) o[(size_t)dd * KCC] = acc[dd] + bv;
    } else {
        float* o = g_Vf + ((size_t)b * KCC + k0 + x) * DD + y * 8;
#pragma unroll
        for (int dd = 0; dd < 8; dd++) o[dd] = acc[dd] + bv;
    }
}

// ---------------------------------------------------------------------------
// Kernel B: fused  P = softmax(mask(Q @ Ke / 8));  out = P @ Vf.
// Grid: (S/256, B). Block: 256 threads (8 warps). Each block loads Ke[b] and
// Vf[b] into SMEM once, then processes 4 passes of 64 rows (8 rows per warp).
// SMEM: Ke 64KB + Vf 64KB + Q tile 16KB + P staging 64KB = 208KB.
// ---------------------------------------------------------------------------
__global__ __launch_bounds__(256) void attn_kernel(
    const float* __restrict__ Q, float* __restrict__ out)
{
    extern __shared__ float sm[];
    float* KeS = sm;                 // [64][256]
    float* VfS = sm + 64 * 256;      // [256][64]
    float* Qs  = sm + 2 * 64 * 256;  // [64][64]
    float* ps  = Qs + 64 * 64;       // [8 warps][256][8]

    const int b    = blockIdx.y;
    const int tile = blockIdx.x;
    const int tid  = threadIdx.x;
    const int lane = tid & 31;
    const int warp = tid >> 5;

    const float* keg = g_Ke + (size_t)b * DD * KCC;
    const float* vfg = g_Vf + (size_t)b * KCC * DD;
#pragma unroll
    for (int t = tid; t < 4096; t += 256)
        reinterpret_cast<float4*>(KeS)[t] = reinterpret_cast<const float4*>(keg)[t];
#pragma unroll
    for (int t = tid; t < 4096; t += 256)
        reinterpret_cast<float4*>(VfS)[t] = reinterpret_cast<const float4*>(vfg)[t];

    const float* Qb = Q + (size_t)b * SS * DD;
    float* pw = ps + warp * (256 * 8);

    for (int pass = 0; pass < 4; pass++) {
        const int s0 = tile * 256 + pass * 64;   // row offset within batch

        __syncthreads();   // protects Qs (and first pass: Ke/Vf load)
#pragma unroll
        for (int t = tid; t < 1024; t += 256)
            reinterpret_cast<float4*>(Qs)[t] =
                reinterpret_cast<const float4*>(Qb + (size_t)s0 * DD)[t];
        __syncthreads();

        const int r0 = warp * 8;

        // ---- GEMM1: P[r][k] = sum_d Q[r][d] * Ke[d][k] ----
        float acc[8][8];
#pragma unroll
        for (int rr = 0; rr < 8; rr++)
#pragma unroll
            for (int kk = 0; kk < 8; kk++) acc[rr][kk] = 0.f;

        for (int d = 0; d < 64; d++) {
            float ke[8];
#pragma unroll
            for (int kk = 0; kk < 8; kk++)
                ke[kk] = KeS[d * 256 + lane + 32 * kk];   // conflict-free
#pragma unroll
            for (int rr = 0; rr < 8; rr++) {
                float q = Qs[(r0 + rr) * 64 + d];         // broadcast
#pragma unroll
                for (int kk = 0; kk < 8; kk++)
                    acc[rr][kk] += q * ke[kk];
            }
        }

        // ---- mask + softmax (row-wise, warp-wide over KC=256) ----
#pragma unroll
        for (int rr = 0; rr < 8; rr++) {
            const int irow = s0 + r0 + rr;
            float m = -3.4e38f;
#pragma unroll
            for (int kk = 0; kk < 8; kk++) {
                int k = lane + 32 * kk;
                float v = (k >= irow) ? acc[rr][kk] * 0.125f : -1e10f;
                acc[rr][kk] = v;
                m = fmaxf(m, v);
            }
#pragma unroll
            for (int o = 16; o > 0; o >>= 1)
                m = fmaxf(m, __shfl_xor_sync(0xffffffffu, m, o));
            float ssum = 0.f;
#pragma unroll
            for (int kk = 0; kk < 8; kk++) {
                float e = __expf(acc[rr][kk] - m);
                acc[rr][kk] = e;
                ssum += e;
            }
#pragma unroll
            for (int o = 16; o > 0; o >>= 1)
                ssum += __shfl_xor_sync(0xffffffffu, ssum, o);
            float inv = 1.f / ssum;
#pragma unroll
            for (int kk = 0; kk < 8; kk++) acc[rr][kk] *= inv;
        }

        // ---- stage P to SMEM (layout [k][rr] for broadcast reads) ----
#pragma unroll
        for (int kk = 0; kk < 8; kk++) {
            int k = lane + 32 * kk;
            float4 v0 = make_float4(acc[0][kk], acc[1][kk], acc[2][kk], acc[3][kk]);
            float4 v1 = make_float4(acc[4][kk], acc[5][kk], acc[6][kk], acc[7][kk]);
            *reinterpret_cast<float4*>(pw + k * 8)     = v0;
            *reinterpret_cast<float4*>(pw + k * 8 + 4) = v1;
        }
        __syncwarp();

        // ---- GEMM2: out[r][d] = sum_k P[r][k] * Vf[k][d], lane owns d=2l,2l+1 ----
        float2 acc2[8];
#pragma unroll
        for (int rr = 0; rr < 8; rr++) acc2[rr] = make_float2(0.f, 0.f);

#pragma unroll 4
        for (int k = 0; k < 256; k++) {
            float4 pa = *reinterpret_cast<const float4*>(pw + k * 8);      // broadcast
            float4 pb = *reinterpret_cast<const float4*>(pw + k * 8 + 4);  // broadcast
            float2 vf = *reinterpret_cast<const float2*>(&VfS[k * 64 + 2 * lane]);
            acc2[0].x += pa.x * vf.x; acc2[0].y += pa.x * vf.y;
            acc2[1].x += pa.y * vf.x; acc2[1].y += pa.y * vf.y;
            acc2[2].x += pa.z * vf.x; acc2[2].y += pa.z * vf.y;
            acc2[3].x += pa.w * vf.x; acc2[3].y += pa.w * vf.y;
            acc2[4].x += pb.x * vf.x; acc2[4].y += pb.x * vf.y;
            acc2[5].x += pb.y * vf.x; acc2[5].y += pb.y * vf.y;
            acc2[6].x += pb.z * vf.x; acc2[6].y += pb.z * vf.y;
            acc2[7].x += pb.w * vf.x; acc2[7].y += pb.w * vf.y;
        }

#pragma unroll
        for (int rr = 0; rr < 8; rr++) {
            int srow = s0 + r0 + rr;
            *reinterpret_cast<float2*>(
                &out[((size_t)b * SS + srow) * DD + 2 * lane]) = acc2[rr];
        }
    }
}

// ---------------------------------------------------------------------------
// Harness entry point. Inputs (metadata order): Q, K, V, E_w, E_b, F_w, F_b.
// Output: float32 [B, S, D].
// ---------------------------------------------------------------------------
extern "C" void kernel_launch(void* const* d_in, const int* in_sizes, int n_in,
                              void* d_out, int out_size)
{
    (void)in_sizes; (void)n_in; (void)out_size;
    const float* Q   = (const float*)d_in[0];
    const float* K   = (const float*)d_in[1];
    const float* V   = (const float*)d_in[2];
    const float* E_w = (const float*)d_in[3];
    const float* E_b = (const float*)d_in[4];
    const float* F_w = (const float*)d_in[5];
    const float* F_b = (const float*)d_in[6];
    float* out = (float*)d_out;

    const int smem_bytes = (64 * 256 + 256 * 64 + 64 * 64 + 8 * 256 * 8) * 4; // 212992
    cudaFuncSetAttribute(attn_kernel,
                         cudaFuncAttributeMaxDynamicSharedMemorySize, smem_bytes);

    dim3 gA(KCC / 32, BB, 2);
    proj_kernel<<<gA, 256>>>(K, V, E_w, E_b, F_w, F_b);

    dim3 gB(SS / 256, BB);
    attn_kernel<<<gB, 256, smem_bytes>>>(Q, out);
}

// round 2
// speedup vs baseline: 1.2567x; 1.2567x over previous
#include <cuda_runtime.h>

#define BB 32
#define SS 4096
#define DD 64
#define KCC 256

// Scratch (device globals — no allocation allowed)
__device__ float g_Ke[BB * DD * KCC];   // [b][d][k]
__device__ float g_Vf[BB * KCC * DD];   // [b][k][d]

// ---------------- packed f32x2 helpers (sm_100+) ----------------
__device__ __forceinline__ unsigned long long pk2(float lo, float hi) {
    unsigned long long r;
    asm("mov.b64 %0, {%1, %2};" : "=l"(r) : "f"(lo), "f"(hi));
    return r;
}
__device__ __forceinline__ unsigned long long dup2(float x) { return pk2(x, x); }
__device__ __forceinline__ void upk2(unsigned long long v, float& lo, float& hi) {
    asm("mov.b64 {%0, %1}, %2;" : "=f"(lo), "=f"(hi) : "l"(v));
}
__device__ __forceinline__ unsigned long long fma2(
    unsigned long long a, unsigned long long b, unsigned long long c) {
    unsigned long long d;
    asm("fma.rn.f32x2 %0, %1, %2, %3;" : "=l"(d) : "l"(a), "l"(b), "l"(c));
    return d;
}

// ---------------------------------------------------------------------------
// Kernel A: projection GEMMs (FFMA2-packed, k-tile = 64).
//   proj==0: g_Ke[b][d][k] = sum_s K[b][s][d] * E_w[k][s] + E_b[k]
//   proj==1: g_Vf[b][k][d] = sum_s V[b][s][d] * F_w[k][s] + F_b[k]
// Grid: (KC/64, B, 2). Block: 256 = (32 k-lanes) x (8 d-groups);
// each thread: 2 k (x, x+32) and 8 d (packed into 4 f32x2 pairs per k).
// ---------------------------------------------------------------------------
__global__ __launch_bounds__(256) void proj_kernel(
    const float* __restrict__ K, const float* __restrict__ V,
    const float* __restrict__ E_w, const float* __restrict__ E_b,
    const float* __restrict__ F_w, const float* __restrict__ F_b)
{
    __shared__ float Xs[64][64];   // [s_local][d]
    __shared__ float Ws[64][65];   // [k_local][s_local], padded

    const int k0   = blockIdx.x * 64;
    const int b    = blockIdx.y;
    const int proj = blockIdx.z;

    const float* __restrict__ X    = proj ? V   : K;
    const float* __restrict__ W    = proj ? F_w : E_w;
    const float* __restrict__ bias = proj ? F_b : E_b;

    const int tid = threadIdx.x;
    const int x   = tid & 31;   // k lane
    const int y   = tid >> 5;   // d group (8 d each)

    unsigned long long acc0[4], acc1[4];
#pragma unroll
    for (int i = 0; i < 4; i++) { acc0[i] = 0ull; acc1[i] = 0ull; }

    const float* Xb = X + (size_t)b * SS * DD;

    for (int s0 = 0; s0 < SS; s0 += 64) {
        // X tile: 64 x 64 floats = 1024 float4 (4/thread, coalesced)
#pragma unroll
        for (int t = tid; t < 64 * 16; t += 256) {
            int r = t >> 4, c = t & 15;
            reinterpret_cast<float4*>(Xs[r])[c] =
                reinterpret_cast<const float4*>(Xb + (size_t)(s0 + r) * DD)[c];
        }
        // W tile: 64 x 64 floats = 1024 float4 (4/thread, coalesced read)
#pragma unroll
        for (int t = tid; t < 64 * 16; t += 256) {
            int kr = t >> 4, c = t & 15;
            float4 v = reinterpret_cast<const float4*>(
                W + (size_t)(k0 + kr) * SS + s0)[c];
            Ws[kr][c * 4 + 0] = v.x;
            Ws[kr][c * 4 + 1] = v.y;
            Ws[kr][c * 4 + 2] = v.z;
            Ws[kr][c * 4 + 3] = v.w;
        }
        __syncthreads();

#pragma unroll 4
        for (int i = 0; i < 64; i++) {
            unsigned long long w0 = dup2(Ws[x][i]);        // conflict-free (pad 65)
            unsigned long long w1 = dup2(Ws[x + 32][i]);
            ulonglong2 u0 = *reinterpret_cast<const ulonglong2*>(&Xs[i][y * 8]);
            ulonglong2 u1 = *reinterpret_cast<const ulonglong2*>(&Xs[i][y * 8 + 4]);
            acc0[0] = fma2(w0, u0.x, acc0[0]);
            acc0[1] = fma2(w0, u0.y, acc0[1]);
            acc0[2] = fma2(w0, u1.x, acc0[2]);
            acc0[3] = fma2(w0, u1.y, acc0[3]);
            acc1[0] = fma2(w1, u0.x, acc1[0]);
            acc1[1] = fma2(w1, u0.y, acc1[1]);
            acc1[2] = fma2(w1, u1.x, acc1[2]);
            acc1[3] = fma2(w1, u1.y, acc1[3]);
        }
        __syncthreads();
    }

    const float bv0 = bias[k0 + x];
    const float bv1 = bias[k0 + x + 32];
    float o0, o1;
    if (proj == 0) {
        float* base = g_Ke + ((size_t)b * DD + y * 8) * KCC + k0 + x;
#pragma unroll
        for (int p = 0; p < 4; p++) {
            upk2(acc0[p], o0, o1);
            base[(size_t)(2 * p) * KCC]     = o0 + bv0;
            base[(size_t)(2 * p + 1) * KCC] = o1 + bv0;
            upk2(acc1[p], o0, o1);
            base[(size_t)(2 * p) * KCC + 32]     = o0 + bv1;
            base[(size_t)(2 * p + 1) * KCC + 32] = o1 + bv1;
        }
    } else {
        float* b0p = g_Vf + ((size_t)b * KCC + k0 + x) * DD + y * 8;
        float* b1p = g_Vf + ((size_t)b * KCC + k0 + x + 32) * DD + y * 8;
#pragma unroll
        for (int p = 0; p < 4; p++) {
            upk2(acc0[p], o0, o1);
            b0p[2 * p] = o0 + bv0; b0p[2 * p + 1] = o1 + bv0;
            upk2(acc1[p], o0, o1);
            b1p[2 * p] = o0 + bv1; b1p[2 * p + 1] = o1 + bv1;
        }
    }
}

// ---------------------------------------------------------------------------
// Kernel B: fused  P = softmax(mask(Q @ Ke / 8));  out = P @ Vf.
// Grid: (S/128, B). Block: 256 (8 warps). Ke[b], Vf[b] resident in SMEM.
// 2 passes of 64 rows; warp owns 8 rows; lane owns k = lane + 32*kk (kk 0..7),
// GEMM1 packed over k-pairs (kk 2m / 2m+1); GEMM2 packed over adjacent k.
// ---------------------------------------------------------------------------
__global__ __launch_bounds__(256) void attn_kernel(
    const float* __restrict__ Q, float* __restrict__ out)
{
    extern __shared__ float sm[];
    float* KeS = sm;                 // [64][256]
    float* VfS = sm + 64 * 256;      // [256][64]
    float* Qs  = sm + 2 * 64 * 256;  // [64][64]
    float* ps  = Qs + 64 * 64;       // [8 warps][8 rr][256 k]

    const int b    = blockIdx.y;
    const int tid  = threadIdx.x;
    const int lane = tid & 31;
    const int warp = tid >> 5;

    const float* keg = g_Ke + (size_t)b * DD * KCC;
    const float* vfg = g_Vf + (size_t)b * KCC * DD;
#pragma unroll
    for (int t = tid; t < 4096; t += 256)
        reinterpret_cast<float4*>(KeS)[t] = reinterpret_cast<const float4*>(keg)[t];
#pragma unroll
    for (int t = tid; t < 4096; t += 256)
        reinterpret_cast<float4*>(VfS)[t] = reinterpret_cast<const float4*>(vfg)[t];

    const float* Qb = Q + (size_t)b * SS * DD;
    float* pw = ps + warp * (8 * 256);   // [rr][k]
    const int r0 = warp * 8;

    for (int pass = 0; pass < 2; pass++) {
        const int s0 = blockIdx.x * 128 + pass * 64;

        __syncthreads();   // protect Qs (and first pass: KeS/VfS loads)
#pragma unroll
        for (int t = tid; t < 1024; t += 256)
            reinterpret_cast<float4*>(Qs)[t] =
                reinterpret_cast<const float4*>(Qb + (size_t)s0 * DD)[t];
        __syncthreads();

        // ---- GEMM1: P[r][k] = sum_d Q[r][d]*Ke[d][k]; packed over k-pairs ----
        // accp[rr][m] = ( P[rr][lane+64m], P[rr][lane+64m+32] )
        unsigned long long accp[8][4];
#pragma unroll
        for (int rr = 0; rr < 8; rr++)
#pragma unroll
            for (int m = 0; m < 4; m++) accp[rr][m] = 0ull;

        for (int d = 0; d < 64; d++) {
            const float* krow = KeS + d * 256 + lane;
            unsigned long long ke[4];
#pragma unroll
            for (int m = 0; m < 4; m++)
                ke[m] = pk2(krow[64 * m], krow[64 * m + 32]);   // stride-1 lanes
#pragma unroll
            for (int rr = 0; rr < 8; rr++) {
                unsigned long long q = dup2(Qs[(r0 + rr) * 64 + d]);  // broadcast
#pragma unroll
                for (int m = 0; m < 4; m++)
                    accp[rr][m] = fma2(q, ke[m], accp[rr][m]);
            }
        }

        __syncwarp();   // pw reuse across passes

        // ---- mask + softmax per row, then stage P as pw[rr][k] ----
#pragma unroll
        for (int rr = 0; rr < 8; rr++) {
            const int irow = s0 + r0 + rr;
            float v[8];
#pragma unroll
            for (int m = 0; m < 4; m++) {
                float lo, hi;
                upk2(accp[rr][m], lo, hi);
                int ke_ = lane + 64 * m;        // even half
                int ko_ = ke_ + 32;             // odd half
                v[2 * m]     = (ke_ >= irow) ? lo * 0.125f : -1e10f;
                v[2 * m + 1] = (ko_ >= irow) ? hi * 0.125f : -1e10f;
            }
            float mx = v[0];
#pragma unroll
            for (int i = 1; i < 8; i++) mx = fmaxf(mx, v[i]);
#pragma unroll
            for (int o = 16; o > 0; o >>= 1)
                mx = fmaxf(mx, __shfl_xor_sync(0xffffffffu, mx, o));
            float ssum = 0.f;
#pragma unroll
            for (int i = 0; i < 8; i++) { v[i] = __expf(v[i] - mx); ssum += v[i]; }
#pragma unroll
            for (int o = 16; o > 0; o >>= 1)
                ssum += __shfl_xor_sync(0xffffffffu, ssum, o);
            float inv = 1.f / ssum;
            float* prow = pw + rr * 256 + lane;
#pragma unroll
            for (int m = 0; m < 4; m++) {
                prow[64 * m]      = v[2 * m] * inv;       // conflict-free STS
                prow[64 * m + 32] = v[2 * m + 1] * inv;
            }
        }
        __syncwarp();

        // ---- GEMM2: out[r][d] = sum_k P[r][k]*Vf[k][d]; packed over k ----
        // lane owns d0 = 2*lane, d1 = 2*lane+1
        unsigned long long a0[8], a1[8];
#pragma unroll
        for (int rr = 0; rr < 8; rr++) { a0[rr] = 0ull; a1[rr] = 0ull; }

#pragma unroll 2
        for (int k = 0; k < 256; k += 2) {
            float2 vfa = *reinterpret_cast<const float2*>(&VfS[k * 64 + 2 * lane]);
            float2 vfb = *reinterpret_cast<const float2*>(&VfS[(k + 1) * 64 + 2 * lane]);
            unsigned long long b0 = pk2(vfa.x, vfb.x);   // (Vf[k][d0], Vf[k+1][d0])
            unsigned long long b1 = pk2(vfa.y, vfb.y);   // (Vf[k][d1], Vf[k+1][d1])
#pragma unroll
            for (int rr = 0; rr < 8; rr++) {
                unsigned long long p =
                    *reinterpret_cast<const unsigned long long*>(pw + rr * 256 + k);
                a0[rr] = fma2(p, b0, a0[rr]);
                a1[rr] = fma2(p, b1, a1[rr]);
            }
        }

#pragma unroll
        for (int rr = 0; rr < 8; rr++) {
            float l0, h0, l1, h1;
            upk2(a0[rr], l0, h0);
            upk2(a1[rr], l1, h1);
            float2 r = make_float2(l0 + h0, l1 + h1);
            *reinterpret_cast<float2*>(
                &out[((size_t)b * SS + s0 + r0 + rr) * DD + 2 * lane]) = r;
        }
    }
}

// ---------------------------------------------------------------------------
// Harness entry. Inputs: Q, K, V, E_w, E_b, F_w, F_b. Output f32 [B,S,D].
// ---------------------------------------------------------------------------
extern "C" void kernel_launch(void* const* d_in, const int* in_sizes, int n_in,
                              void* d_out, int out_size)
{
    (void)in_sizes; (void)n_in; (void)out_size;
    const float* Q   = (const float*)d_in[0];
    const float* K   = (const float*)d_in[1];
    const float* V   = (const float*)d_in[2];
    const float* E_w = (const float*)d_in[3];
    const float* E_b = (const float*)d_in[4];
    const float* F_w = (const float*)d_in[5];
    const float* F_b = (const float*)d_in[6];
    float* out = (float*)d_out;

    const int smem_bytes =
        (64 * 256 + 256 * 64 + 64 * 64 + 8 * 8 * 256) * 4;   // 212992 B
    cudaFuncSetAttribute(attn_kernel,
                         cudaFuncAttributeMaxDynamicSharedMemorySize, smem_bytes);

    dim3 gA(KCC / 64, BB, 2);
    proj_kernel<<<gA, 256>>>(K, V, E_w, E_b, F_w, F_b);

    dim3 gB(SS / 128, BB);
    attn_kernel<<<gB, 256, smem_bytes>>>(Q, out);
}

// round 4
// speedup vs baseline: 1.8289x; 1.4553x over previous
#include <cuda_runtime.h>
#include <cuda_bf16.h>
#include <cstdint>

#define BB 32
#define SS 4096
#define DD 64
#define KCC 256

// ------------------------- device global scratch ---------------------------
__device__ float g_Ke[BB * DD * KCC];              // [b][d][k]
__device__ float g_Vf[BB * KCC * DD];              // [b][k][d]
__device__ __nv_bfloat16 g_Wh[2 * KCC * SS];       // [proj][kc][s] hi
__device__ __nv_bfloat16 g_Wl[2 * KCC * SS];       // [proj][kc][s] lo
__device__ __nv_bfloat16 g_Xh[2 * BB * SS * DD];   // [proj][b][s][d] hi (natural layout)
__device__ __nv_bfloat16 g_Xl[2 * BB * SS * DD];   // lo

// ------------------------------ helpers ------------------------------------
__device__ __forceinline__ uint32_t smem_u32(const void* p) {
    uint32_t a;
    asm("{ .reg .u64 t; cvta.to.shared.u64 t, %1; cvt.u32.u64 %0, t; }"
        : "=r"(a) : "l"(p));
    return a;
}
#define SW128(x) ((x) ^ (((x) >> 3) & 0x70))

__device__ __forceinline__ void cp16(uint32_t dst, const void* src) {
    asm volatile("cp.async.cg.shared.global [%0], [%1], 16;"
                 :: "r"(dst), "l"(src) : "memory");
}
__device__ __forceinline__ void cp_commit() {
    asm volatile("cp.async.commit_group;" ::: "memory");
}
template <int N>
__device__ __forceinline__ void cp_wait() {
    asm volatile("cp.async.wait_group %0;" :: "n"(N) : "memory");
}
__device__ __forceinline__ void ldm_x4(uint32_t* r, uint32_t addr) {
    asm volatile("ldmatrix.sync.aligned.m8n8.x4.shared.b16 {%0,%1,%2,%3}, [%4];"
                 : "=r"(r[0]), "=r"(r[1]), "=r"(r[2]), "=r"(r[3]) : "r"(addr));
}
__device__ __forceinline__ void ldm_x4_t(uint32_t* r, uint32_t addr) {
    asm volatile("ldmatrix.sync.aligned.m8n8.x4.trans.shared.b16 {%0,%1,%2,%3}, [%4];"
                 : "=r"(r[0]), "=r"(r[1]), "=r"(r[2]), "=r"(r[3]) : "r"(addr));
}
__device__ __forceinline__ void mma_bf16(
    float* c, const uint32_t* a, uint32_t b0, uint32_t b1) {
    asm volatile(
        "mma.sync.aligned.m16n8k16.row.col.f32.bf16.bf16.f32 "
        "{%0,%1,%2,%3}, {%4,%5,%6,%7}, {%8,%9}, {%0,%1,%2,%3};"
        : "+f"(c[0]), "+f"(c[1]), "+f"(c[2]), "+f"(c[3])
        : "r"(a[0]), "r"(a[1]), "r"(a[2]), "r"(a[3]), "r"(b0), "r"(b1));
}

// ---------------- packed f32x2 helpers (attn kernel) ----------------
__device__ __forceinline__ unsigned long long pk2(float lo, float hi) {
    unsigned long long r;
    asm("mov.b64 %0, {%1, %2};" : "=l"(r) : "f"(lo), "f"(hi));
    return r;
}
__device__ __forceinline__ void upk2(unsigned long long v, float& lo, float& hi) {
    asm("mov.b64 {%0, %1}, %2;" : "=f"(lo), "=f"(hi) : "l"(v));
}
__device__ __forceinline__ unsigned long long fma2(
    unsigned long long a, unsigned long long b, unsigned long long c) {
    unsigned long long d;
    asm("fma.rn.f32x2 %0, %1, %2, %3;" : "=l"(d) : "l"(a), "l"(b), "l"(c));
    return d;
}

// ---------------------------------------------------------------------------
// conv_w: E_w / F_w (fp32 [256][4096]) -> bf16 hi/lo, same layout.
// Grid (1024, 2), block 256; one float4 per thread.
// ---------------------------------------------------------------------------
__global__ __launch_bounds__(256) void conv_w_kernel(
    const float* __restrict__ Ew, const float* __restrict__ Fw)
{
    const int y = blockIdx.y;
    const float4* src = reinterpret_cast<const float4*>(y ? Fw : Ew);
    const int i = blockIdx.x * 256 + threadIdx.x;
    float4 v = src[i];
    __nv_bfloat16 h0 = __float2bfloat16(v.x), h1 = __float2bfloat16(v.y),
                  h2 = __float2bfloat16(v.z), h3 = __float2bfloat16(v.w);
    __nv_bfloat16 l0 = __float2bfloat16(v.x - __bfloat162float(h0));
    __nv_bfloat16 l1 = __float2bfloat16(v.y - __bfloat162float(h1));
    __nv_bfloat16 l2 = __float2bfloat16(v.z - __bfloat162float(h2));
    __nv_bfloat16 l3 = __float2bfloat16(v.w - __bfloat162float(h3));
    __nv_bfloat162* oh = reinterpret_cast<__nv_bfloat162*>(
        g_Wh + (size_t)y * KCC * SS) + 2 * i;
    __nv_bfloat162* ol = reinterpret_cast<__nv_bfloat162*>(
        g_Wl + (size_t)y * KCC * SS) + 2 * i;
    oh[0] = __halves2bfloat162(h0, h1);
    oh[1] = __halves2bfloat162(h2, h3);
    ol[0] = __halves2bfloat162(l0, l1);
    ol[1] = __halves2bfloat162(l2, l3);
}

// ---------------------------------------------------------------------------
// conv_x: K / V (fp32 [b][s][d]) -> bf16 hi/lo, SAME layout (no transpose).
// Grid (8192, 2), block 256; one float4 per thread.
// ---------------------------------------------------------------------------
__global__ __launch_bounds__(256) void conv_x_kernel(
    const float* __restrict__ K, const float* __restrict__ V)
{
    const int y = blockIdx.y;
    const float4* src = reinterpret_cast<const float4*>(y ? V : K);
    const size_t i = (size_t)blockIdx.x * 256 + threadIdx.x;
    float4 v = src[i];
    __nv_bfloat16 h0 = __float2bfloat16(v.x), h1 = __float2bfloat16(v.y),
                  h2 = __float2bfloat16(v.z), h3 = __float2bfloat16(v.w);
    __nv_bfloat16 l0 = __float2bfloat16(v.x - __bfloat162float(h0));
    __nv_bfloat16 l1 = __float2bfloat16(v.y - __bfloat162float(h1));
    __nv_bfloat16 l2 = __float2bfloat16(v.z - __bfloat162float(h2));
    __nv_bfloat16 l3 = __float2bfloat16(v.w - __bfloat162float(h3));
    __nv_bfloat162* oh = reinterpret_cast<__nv_bfloat162*>(
        g_Xh + (size_t)y * BB * SS * DD) + 2 * i;
    __nv_bfloat162* ol = reinterpret_cast<__nv_bfloat162*>(
        g_Xl + (size_t)y * BB * SS * DD) + 2 * i;
    oh[0] = __halves2bfloat162(h0, h1);
    oh[1] = __halves2bfloat162(h2, h3);
    ol[0] = __halves2bfloat162(l0, l1);
    ol[1] = __halves2bfloat162(l2, l3);
}

// ---------------------------------------------------------------------------
// proj_mma: mma.sync bf16 3-split GEMM.
//   D[kc][d] = sum_s W[kc][s] * X[s][d]   (M=128 kc, N=64 d, K=4096 s)
// Grid (2, B, 2). Block 256 (8 warps = 2 m-groups x 4 n-groups; warp tile
// M=64 x N=16). Double-buffered cp.async; SW128-swizzled SMEM; ldmatrix.
// SMEM per buf: Ah 16K | Al 16K | Bh 8K | Bl 8K = 48K; x2 = 96K.
// ---------------------------------------------------------------------------
__global__ __launch_bounds__(256) void proj_mma_kernel(
    const float* __restrict__ E_b, const float* __restrict__ F_b)
{
    extern __shared__ char sm[];
    const uint32_t smb = smem_u32(sm);
    const int tid = threadIdx.x, wid = tid >> 5, lane = tid & 31;
    const int kc0 = blockIdx.x * 128, b = blockIdx.y, proj = blockIdx.z;
    const int mw = wid >> 2, nw = wid & 3;          // warp tile: m 64, n 16
    const int g = lane >> 2, q = lane & 3;

    const __nv_bfloat16* Wh = g_Wh + ((size_t)proj * KCC + kc0) * SS;
    const __nv_bfloat16* Wl = g_Wl + ((size_t)proj * KCC + kc0) * SS;
    const __nv_bfloat16* Xh = g_Xh + ((size_t)proj * BB + b) * SS * DD;
    const __nv_bfloat16* Xl = g_Xl + ((size_t)proj * BB + b) * SS * DD;

    float acc[4][2][4];                              // [mf][nf][c0..c3]
#pragma unroll
    for (int mf = 0; mf < 4; mf++)
#pragma unroll
        for (int nf = 0; nf < 2; nf++)
#pragma unroll
            for (int i = 0; i < 4; i++) acc[mf][nf][i] = 0.f;

    const int NC = SS / 64;                          // 64 chunks of k=64

    // ---- chunk loader: A 128x64 bf16 (hi+lo), B 64x64 bf16 (hi+lo) ----
    auto load_chunk = [&](int c) {
        const uint32_t buf = smb + (c & 1) * 49152;
#pragma unroll
        for (int idx = tid; idx < 1024; idx += 256) {       // A tiles
            int row = idx >> 3, s16 = idx & 7;
            size_t so = (size_t)row * SS + c * 64 + s16 * 8;
            uint32_t bo = SW128((uint32_t)(row * 128 + s16 * 16));
            cp16(buf + bo,         Wh + so);
            cp16(buf + 16384 + bo, Wl + so);
        }
#pragma unroll
        for (int idx = tid; idx < 512; idx += 256) {        // B tiles
            int row = idx >> 3, s16 = idx & 7;
            size_t so = (size_t)(c * 64 + row) * DD + s16 * 8;
            uint32_t bo = SW128((uint32_t)(row * 128 + s16 * 16));
            cp16(buf + 32768 + bo, Xh + so);
            cp16(buf + 40960 + bo, Xl + so);
        }
        cp_commit();
    };

    load_chunk(0);

    for (int c = 0; c < NC; c++) {
        if (c + 1 < NC) { load_chunk(c + 1); cp_wait<1>(); }
        else           { cp_wait<0>(); }
        __syncthreads();

        const uint32_t buf = smb + (c & 1) * 49152;
        const uint32_t Ah = buf, Al = buf + 16384;
        const uint32_t Bh = buf + 32768, Bl = buf + 40960;

        // per-lane ldmatrix row/col offsets
        const int lr = lane & 15, lc = (lane >> 4) * 16;

#pragma unroll
        for (int kk = 0; kk < 4; kk++) {                     // k16 steps
            uint32_t bh[4], bl[4];
            {
                uint32_t off = SW128((uint32_t)(
                    (kk * 16 + lr) * 128 + nw * 32 + lc));
                ldm_x4_t(bh, Bh + off);
                ldm_x4_t(bl, Bl + off);
            }
#pragma unroll
            for (int mf = 0; mf < 4; mf++) {
                uint32_t ah[4], al[4];
                uint32_t off = SW128((uint32_t)(
                    (mw * 64 + mf * 16 + lr) * 128 + kk * 32 + lc));
                ldm_x4(ah, Ah + off);
                ldm_x4(al, Al + off);
#pragma unroll
                for (int nf = 0; nf < 2; nf++) {
                    mma_bf16(acc[mf][nf], ah, bh[2 * nf], bh[2 * nf + 1]);
                    mma_bf16(acc[mf][nf], al, bh[2 * nf], bh[2 * nf + 1]);
                    mma_bf16(acc[mf][nf], ah, bl[2 * nf], bl[2 * nf + 1]);
                }
            }
        }
        __syncthreads();
    }

    // ---- epilogue: add bias, store ----
    const float* bias = proj ? F_b : E_b;
#pragma unroll
    for (int mf = 0; mf < 4; mf++) {
        const int kcl = mw * 64 + mf * 16 + g;       // local kc (and kcl+8)
        const float bv0 = bias[kc0 + kcl];
        const float bv8 = bias[kc0 + kcl + 8];
#pragma unroll
        for (int nf = 0; nf < 2; nf++) {
            const int d0 = nw * 16 + nf * 8 + 2 * q;
            if (proj == 0) {
                float* o = g_Ke + (size_t)b * DD * KCC + kc0;
                o[(size_t)d0 * KCC + kcl]           = acc[mf][nf][0] + bv0;
                o[(size_t)(d0 + 1) * KCC + kcl]     = acc[mf][nf][1] + bv0;
                o[(size_t)d0 * KCC + kcl + 8]       = acc[mf][nf][2] + bv8;
                o[(size_t)(d0 + 1) * KCC + kcl + 8] = acc[mf][nf][3] + bv8;
            } else {
                float* o = g_Vf + (size_t)b * KCC * DD + (size_t)kc0 * DD;
                *reinterpret_cast<float2*>(&o[(size_t)kcl * DD + d0]) =
                    make_float2(acc[mf][nf][0] + bv0, acc[mf][nf][1] + bv0);
                *reinterpret_cast<float2*>(&o[(size_t)(kcl + 8) * DD + d0]) =
                    make_float2(acc[mf][nf][2] + bv8, acc[mf][nf][3] + bv8);
            }
        }
    }
}

// ---------------------------------------------------------------------------
// attn: fused P = softmax(mask(Q @ Ke / 8)); out = P @ Vf.   (FFMA2, de-ALU'd)
// Grid (S/128, B). Block 256 (8 warps), 2 passes of 64 rows, 8 rows/warp.
// Lane owns k in {64m + 2*lane, +1}; adjacent pairs -> LDS.64, no packs.
// Q stored pre-duplicated (float2) -> no dup movs.
// SMEM: Ke 64K | Vf 64K | Qdup 32K | pw 64K = 224K.
// ---------------------------------------------------------------------------
__global__ __launch_bounds__(256) void attn_kernel(
    const float* __restrict__ Q, float* __restrict__ out)
{
    extern __shared__ float smf[];
    float* KeS = smf;                  // [64][256]
    float* VfS = smf + 16384;          // [256][64]
    float* Qd  = smf + 32768;          // [64][64] duplicated (x2)
    float* ps  = smf + 40960;          // [8 warps][8 rr][256 k]

    const int b = blockIdx.y;
    const int tid = threadIdx.x, lane = tid & 31, warp = tid >> 5;

    const float* keg = g_Ke + (size_t)b * DD * KCC;
    const float* vfg = g_Vf + (size_t)b * KCC * DD;
#pragma unroll
    for (int t = tid; t < 4096; t += 256)
        reinterpret_cast<float4*>(KeS)[t] = reinterpret_cast<const float4*>(keg)[t];
#pragma unroll
    for (int t = tid; t < 4096; t += 256)
        reinterpret_cast<float4*>(VfS)[t] = reinterpret_cast<const float4*>(vfg)[t];

    const float* Qb = Q + (size_t)b * SS * DD;
    float* pw = ps + warp * (8 * 256);
    const int r0 = warp * 8;

    for (int pass = 0; pass < 2; pass++) {
        const int s0 = blockIdx.x * 128 + pass * 64;

        __syncthreads();   // protect Qd (and first pass: KeS/VfS loads)
#pragma unroll
        for (int t = tid; t < 1024; t += 256) {
            int r = t >> 4, c4 = t & 15;
            float4 f = *reinterpret_cast<const float4*>(
                Qb + (size_t)(s0 + r) * DD + c4 * 4);
            float* dst = Qd + (r * 64 + c4 * 4) * 2;
            *reinterpret_cast<float4*>(dst)     = make_float4(f.x, f.x, f.y, f.y);
            *reinterpret_cast<float4*>(dst + 4) = make_float4(f.z, f.z, f.w, f.w);
        }
        __syncthreads();

        // ---- GEMM1: packed over adjacent k ----
        unsigned long long accp[8][4];
#pragma unroll
        for (int rr = 0; rr < 8; rr++)
#pragma unroll
            for (int m = 0; m < 4; m++) accp[rr][m] = 0ull;

        for (int d = 0; d < 64; d++) {
            const float* krow = KeS + d * 256 + 2 * lane;
            unsigned long long ke[4];
#pragma unroll
            for (int m = 0; m < 4; m++)
                ke[m] = *reinterpret_cast<const unsigned long long*>(krow + 64 * m);
#pragma unroll
            for (int rr = 0; rr < 8; rr++) {
                unsigned long long qv = *reinterpret_cast<const unsigned long long*>(
                    Qd + ((r0 + rr) * 64 + d) * 2);   // broadcast LDS.64
#pragma unroll
                for (int m = 0; m < 4; m++)
                    accp[rr][m] = fma2(qv, ke[m], accp[rr][m]);
            }
        }

        __syncwarp();   // pw reuse across passes

        // ---- mask + softmax; stage P as pw[rr][k] ----
#pragma unroll
        for (int rr = 0; rr < 8; rr++) {
            const int irow = s0 + r0 + rr;
            float v[8];
#pragma unroll
            for (int m = 0; m < 4; m++) {
                float lo, hi;
                upk2(accp[rr][m], lo, hi);
                int ke_ = 64 * m + 2 * lane;
                v[2 * m]     = (ke_ >= irow)     ? lo * 0.125f : -1e10f;
                v[2 * m + 1] = (ke_ + 1 >= irow) ? hi * 0.125f : -1e10f;
            }
            float mx = v[0];
#pragma unroll
            for (int i = 1; i < 8; i++) mx = fmaxf(mx, v[i]);
#pragma unroll
            for (int o = 16; o > 0; o >>= 1)
                mx = fmaxf(mx, __shfl_xor_sync(0xffffffffu, mx, o));
            float ssum = 0.f;
#pragma unroll
            for (int i = 0; i < 8; i++) { v[i] = __expf(v[i] - mx); ssum += v[i]; }
#pragma unroll
            for (int o = 16; o > 0; o >>= 1)
                ssum += __shfl_xor_sync(0xffffffffu, ssum, o);
            float inv = 1.f / ssum;
            float* prow = pw + rr * 256 + 2 * lane;
#pragma unroll
            for (int m = 0; m < 4; m++)
                *reinterpret_cast<float2*>(prow + 64 * m) =
                    make_float2(v[2 * m] * inv, v[2 * m + 1] * inv);
        }
        __syncwarp();

        // ---- GEMM2: packed over k ----
        unsigned long long a0[8], a1[8];
#pragma unroll
        for (int rr = 0; rr < 8; rr++) { a0[rr] = 0ull; a1[rr] = 0ull; }

#pragma unroll 2
        for (int k = 0; k < 256; k += 2) {
            float2 vfa = *reinterpret_cast<const float2*>(&VfS[k * 64 + 2 * lane]);
            float2 vfb = *reinterpret_cast<const float2*>(&VfS[(k + 1) * 64 + 2 * lane]);
            unsigned long long b0 = pk2(vfa.x, vfb.x);
            unsigned long long b1 = pk2(vfa.y, vfb.y);
#pragma unroll
            for (int rr = 0; rr < 8; rr++) {
                unsigned long long p =
                    *reinterpret_cast<const unsigned long long*>(pw + rr * 256 + k);
                a0[rr] = fma2(p, b0, a0[rr]);
                a1[rr] = fma2(p, b1, a1[rr]);
            }
        }

#pragma unroll
        for (int rr = 0; rr < 8; rr++) {
            float l0, h0, l1, h1;
            upk2(a0[rr], l0, h0);
            upk2(a1[rr], l1, h1);
            *reinterpret_cast<float2*>(
                &out[((size_t)b * SS + s0 + r0 + rr) * DD + 2 * lane]) =
                make_float2(l0 + h0, l1 + h1);
        }
    }
}

// ---------------------------------------------------------------------------
// Harness entry. Inputs: Q, K, V, E_w, E_b, F_w, F_b. Output f32 [B,S,D].
// ---------------------------------------------------------------------------
extern "C" void kernel_launch(void* const* d_in, const int* in_sizes, int n_in,
                              void* d_out, int out_size)
{
    (void)in_sizes; (void)n_in; (void)out_size;
    const float* Q   = (const float*)d_in[0];
    const float* K   = (const float*)d_in[1];
    const float* V   = (const float*)d_in[2];
    const float* E_w = (const float*)d_in[3];
    const float* E_b = (const float*)d_in[4];
    const float* F_w = (const float*)d_in[5];
    const float* F_b = (const float*)d_in[6];
    float* out = (float*)d_out;

    const int proj_smem = 2 * 49152;                           // 98304
    const int attn_smem = (16384 + 16384 + 8192 + 16384) * 4;  // 229376
    cudaFuncSetAttribute(proj_mma_kernel,
                         cudaFuncAttributeMaxDynamicSharedMemorySize, proj_smem);
    cudaFuncSetAttribute(attn_kernel,
                         cudaFuncAttributeMaxDynamicSharedMemorySize, attn_smem);

    conv_w_kernel<<<dim3(1024, 2), 256>>>(E_w, F_w);
    conv_x_kernel<<<dim3(8192, 2), 256>>>(K, V);
    proj_mma_kernel<<<dim3(2, BB, 2), 256, proj_smem>>>(E_b, F_b);
    attn_kernel<<<dim3(SS / 128, BB), 256, attn_smem>>>(Q, out);
}

// round 5
// speedup vs baseline: 3.9839x; 2.1783x over previous
#include <cuda_runtime.h>
#include <cuda_bf16.h>
#include <cstdint>

#define BB 32
#define SS 4096
#define DD 64
#define KCC 256

// ------------------------- device global scratch ---------------------------
__device__ __nv_bfloat16 g_Wh[2 * KCC * SS];       // [proj][kc][s] hi
__device__ __nv_bfloat16 g_Wl[2 * KCC * SS];       // lo
__device__ __nv_bfloat16 g_Qh[BB * SS * DD];       // [b][s][d] hi
__device__ __nv_bfloat16 g_Ql[BB * SS * DD];       // lo
__device__ __nv_bfloat16 g_Xh[2 * BB * SS * DD];   // [K/V][b][s][d] hi
__device__ __nv_bfloat16 g_Xl[2 * BB * SS * DD];   // lo
__device__ __nv_bfloat16 g_Keh[BB * KCC * DD];     // [b][kc][d] hi   (= Ke^T)
__device__ __nv_bfloat16 g_Kel[BB * KCC * DD];     // lo
__device__ __nv_bfloat16 g_Vfh[BB * KCC * DD];     // [b][kc][d] hi
__device__ __nv_bfloat16 g_Vfl[BB * KCC * DD];     // lo

// ------------------------------ helpers ------------------------------------
__device__ __forceinline__ uint32_t smem_u32(const void* p) {
    uint32_t a;
    asm("{ .reg .u64 t; cvta.to.shared.u64 t, %1; cvt.u32.u64 %0, t; }"
        : "=r"(a) : "l"(p));
    return a;
}
#define SW128(x) ((x) ^ (((x) >> 3) & 0x70))

__device__ __forceinline__ void cp16(uint32_t dst, const void* src) {
    asm volatile("cp.async.cg.shared.global [%0], [%1], 16;"
                 :: "r"(dst), "l"(src) : "memory");
}
__device__ __forceinline__ void cp_commit() {
    asm volatile("cp.async.commit_group;" ::: "memory");
}
template <int N>
__device__ __forceinline__ void cp_wait() {
    asm volatile("cp.async.wait_group %0;" :: "n"(N) : "memory");
}
__device__ __forceinline__ void ldm_x4(uint32_t* r, uint32_t addr) {
    asm volatile("ldmatrix.sync.aligned.m8n8.x4.shared.b16 {%0,%1,%2,%3}, [%4];"
                 : "=r"(r[0]), "=r"(r[1]), "=r"(r[2]), "=r"(r[3]) : "r"(addr));
}
__device__ __forceinline__ void ldm_x4_t(uint32_t* r, uint32_t addr) {
    asm volatile("ldmatrix.sync.aligned.m8n8.x4.trans.shared.b16 {%0,%1,%2,%3}, [%4];"
                 : "=r"(r[0]), "=r"(r[1]), "=r"(r[2]), "=r"(r[3]) : "r"(addr));
}
__device__ __forceinline__ void mma_bf16(
    float* c, const uint32_t* a, uint32_t b0, uint32_t b1) {
    asm volatile(
        "mma.sync.aligned.m16n8k16.row.col.f32.bf16.bf16.f32 "
        "{%0,%1,%2,%3}, {%4,%5,%6,%7}, {%8,%9}, {%0,%1,%2,%3};"
        : "+f"(c[0]), "+f"(c[1]), "+f"(c[2]), "+f"(c[3])
        : "r"(a[0]), "r"(a[1]), "r"(a[2]), "r"(a[3]), "r"(b0), "r"(b1));
}
// pack two fp32 -> bf16x2 (lo in low half)
__device__ __forceinline__ uint32_t packbf(float lo, float hi) {
    uint32_t r;
    asm("cvt.rn.bf16x2.f32 %0, %1, %2;" : "=r"(r) : "f"(hi), "f"(lo));
    return r;
}

// ---------------------------------------------------------------------------
// conv_w: E_w / F_w (fp32 [256][4096]) -> bf16 hi/lo, same layout.
// ---------------------------------------------------------------------------
__global__ __launch_bounds__(256) void conv_w_kernel(
    const float* __restrict__ Ew, const float* __restrict__ Fw)
{
    const int y = blockIdx.y;
    const float4* src = reinterpret_cast<const float4*>(y ? Fw : Ew);
    const int i = blockIdx.x * 256 + threadIdx.x;
    float4 v = src[i];
    __nv_bfloat16 h0 = __float2bfloat16(v.x), h1 = __float2bfloat16(v.y),
                  h2 = __float2bfloat16(v.z), h3 = __float2bfloat16(v.w);
    __nv_bfloat16 l0 = __float2bfloat16(v.x - __bfloat162float(h0));
    __nv_bfloat16 l1 = __float2bfloat16(v.y - __bfloat162float(h1));
    __nv_bfloat16 l2 = __float2bfloat16(v.z - __bfloat162float(h2));
    __nv_bfloat16 l3 = __float2bfloat16(v.w - __bfloat162float(h3));
    __nv_bfloat162* oh = reinterpret_cast<__nv_bfloat162*>(
        g_Wh + (size_t)y * KCC * SS) + 2 * i;
    __nv_bfloat162* ol = reinterpret_cast<__nv_bfloat162*>(
        g_Wl + (size_t)y * KCC * SS) + 2 * i;
    oh[0] = __halves2bfloat162(h0, h1);
    oh[1] = __halves2bfloat162(h2, h3);
    ol[0] = __halves2bfloat162(l0, l1);
    ol[1] = __halves2bfloat162(l2, l3);
}

// ---------------------------------------------------------------------------
// conv_qkv: Q / K / V (fp32 [b][s][d]) -> bf16 hi/lo, same layout.
// Grid (8192, 3): z = 0 -> Q, 1 -> K, 2 -> V.
// ---------------------------------------------------------------------------
__global__ __launch_bounds__(256) void conv_qkv_kernel(
    const float* __restrict__ Q, const float* __restrict__ K,
    const float* __restrict__ V)
{
    const int z = blockIdx.y;
    const float4* src = reinterpret_cast<const float4*>(
        z == 0 ? Q : (z == 1 ? K : V));
    const size_t i = (size_t)blockIdx.x * 256 + threadIdx.x;
    float4 v = src[i];
    __nv_bfloat16 h0 = __float2bfloat16(v.x), h1 = __float2bfloat16(v.y),
                  h2 = __float2bfloat16(v.z), h3 = __float2bfloat16(v.w);
    __nv_bfloat16 l0 = __float2bfloat16(v.x - __bfloat162float(h0));
    __nv_bfloat16 l1 = __float2bfloat16(v.y - __bfloat162float(h1));
    __nv_bfloat16 l2 = __float2bfloat16(v.z - __bfloat162float(h2));
    __nv_bfloat16 l3 = __float2bfloat16(v.w - __bfloat162float(h3));
    __nv_bfloat16* dh = z == 0 ? g_Qh : g_Xh + (size_t)(z - 1) * BB * SS * DD;
    __nv_bfloat16* dl = z == 0 ? g_Ql : g_Xl + (size_t)(z - 1) * BB * SS * DD;
    __nv_bfloat162* oh = reinterpret_cast<__nv_bfloat162*>(dh) + 2 * i;
    __nv_bfloat162* ol = reinterpret_cast<__nv_bfloat162*>(dl) + 2 * i;
    oh[0] = __halves2bfloat162(h0, h1);
    oh[1] = __halves2bfloat162(h2, h3);
    ol[0] = __halves2bfloat162(l0, l1);
    ol[1] = __halves2bfloat162(l2, l3);
}

// ---------------------------------------------------------------------------
// proj_mma: mma.sync bf16 3-split GEMM.
//   D[kc][d] = sum_s W[kc][s] * X[s][d]   (M=128 kc, N=64 d, K=4096 s)
// Grid (2, B, 2). Block 256 (2 m-groups x 4 n-groups; warp tile 64x16).
// Epilogue: bias add, split to bf16 hi/lo, store [b][kc][d].
// ---------------------------------------------------------------------------
__global__ __launch_bounds__(256) void proj_mma_kernel(
    const float* __restrict__ E_b, const float* __restrict__ F_b)
{
    extern __shared__ char sm[];
    const uint32_t smb = smem_u32(sm);
    const int tid = threadIdx.x, wid = tid >> 5, lane = tid & 31;
    const int kc0 = blockIdx.x * 128, b = blockIdx.y, proj = blockIdx.z;
    const int mw = wid >> 2, nw = wid & 3;
    const int g = lane >> 2, q = lane & 3;

    const __nv_bfloat16* Wh = g_Wh + ((size_t)proj * KCC + kc0) * SS;
    const __nv_bfloat16* Wl = g_Wl + ((size_t)proj * KCC + kc0) * SS;
    const __nv_bfloat16* Xh = g_Xh + ((size_t)proj * BB + b) * SS * DD;
    const __nv_bfloat16* Xl = g_Xl + ((size_t)proj * BB + b) * SS * DD;

    float acc[4][2][4];
#pragma unroll
    for (int mf = 0; mf < 4; mf++)
#pragma unroll
        for (int nf = 0; nf < 2; nf++)
#pragma unroll
            for (int i = 0; i < 4; i++) acc[mf][nf][i] = 0.f;

    const int NC = SS / 64;

    auto load_chunk = [&](int c) {
        const uint32_t buf = smb + (c & 1) * 49152;
#pragma unroll
        for (int idx = tid; idx < 1024; idx += 256) {
            int row = idx >> 3, s16 = idx & 7;
            size_t so = (size_t)row * SS + c * 64 + s16 * 8;
            uint32_t bo = SW128((uint32_t)(row * 128 + s16 * 16));
            cp16(buf + bo,         Wh + so);
            cp16(buf + 16384 + bo, Wl + so);
        }
#pragma unroll
        for (int idx = tid; idx < 512; idx += 256) {
            int row = idx >> 3, s16 = idx & 7;
            size_t so = (size_t)(c * 64 + row) * DD + s16 * 8;
            uint32_t bo = SW128((uint32_t)(row * 128 + s16 * 16));
            cp16(buf + 32768 + bo, Xh + so);
            cp16(buf + 40960 + bo, Xl + so);
        }
        cp_commit();
    };

    load_chunk(0);

    for (int c = 0; c < NC; c++) {
        if (c + 1 < NC) { load_chunk(c + 1); cp_wait<1>(); }
        else           { cp_wait<0>(); }
        __syncthreads();

        const uint32_t buf = smb + (c & 1) * 49152;
        const uint32_t Ah = buf, Al = buf + 16384;
        const uint32_t Bh = buf + 32768, Bl = buf + 40960;
        const int lr = lane & 15, lc = (lane >> 4) * 16;

#pragma unroll
        for (int kk = 0; kk < 4; kk++) {
            uint32_t bh[4], bl[4];
            {
                uint32_t off = SW128((uint32_t)(
                    (kk * 16 + lr) * 128 + nw * 32 + lc));
                ldm_x4_t(bh, Bh + off);
                ldm_x4_t(bl, Bl + off);
            }
#pragma unroll
            for (int mf = 0; mf < 4; mf++) {
                uint32_t ah[4], al[4];
                uint32_t off = SW128((uint32_t)(
                    (mw * 64 + mf * 16 + lr) * 128 + kk * 32 + lc));
                ldm_x4(ah, Ah + off);
                ldm_x4(al, Al + off);
#pragma unroll
                for (int nf = 0; nf < 2; nf++) {
                    mma_bf16(acc[mf][nf], ah, bh[2 * nf], bh[2 * nf + 1]);
                    mma_bf16(acc[mf][nf], al, bh[2 * nf], bh[2 * nf + 1]);
                    mma_bf16(acc[mf][nf], ah, bl[2 * nf], bl[2 * nf + 1]);
                }
            }
        }
        __syncthreads();
    }

    // ---- epilogue: bias add, bf16 hi/lo split, store [b][kc][d] ----
    const float* bias = proj ? F_b : E_b;
    __nv_bfloat16* oh = (proj ? g_Vfh : g_Keh) + ((size_t)b * KCC + kc0) * DD;
    __nv_bfloat16* ol = (proj ? g_Vfl : g_Kel) + ((size_t)b * KCC + kc0) * DD;
#pragma unroll
    for (int mf = 0; mf < 4; mf++) {
        const int kcl = mw * 64 + mf * 16 + g;
        const float bv0 = bias[kc0 + kcl];
        const float bv8 = bias[kc0 + kcl + 8];
#pragma unroll
        for (int nf = 0; nf < 2; nf++) {
            const int d0 = nw * 16 + nf * 8 + 2 * q;
            float v0 = acc[mf][nf][0] + bv0, v1 = acc[mf][nf][1] + bv0;
            float v2 = acc[mf][nf][2] + bv8, v3 = acc[mf][nf][3] + bv8;
            uint32_t h01 = packbf(v0, v1);
            uint32_t h23 = packbf(v2, v3);
            float r0 = v0 - __bfloat162float(__float2bfloat16(v0));
            float r1 = v1 - __bfloat162float(__float2bfloat16(v1));
            float r2 = v2 - __bfloat162float(__float2bfloat16(v2));
            float r3 = v3 - __bfloat162float(__float2bfloat16(v3));
            *reinterpret_cast<uint32_t*>(&oh[(size_t)kcl * DD + d0]) = h01;
            *reinterpret_cast<uint32_t*>(&oh[(size_t)(kcl + 8) * DD + d0]) = h23;
            *reinterpret_cast<uint32_t*>(&ol[(size_t)kcl * DD + d0]) = packbf(r0, r1);
            *reinterpret_cast<uint32_t*>(&ol[(size_t)(kcl + 8) * DD + d0]) = packbf(r2, r3);
        }
    }
}

// ---------------------------------------------------------------------------
// attn: fully tensor-core fused attention.
//   P = softmax(mask(Q @ Ke^T / 8));  out = P @ Vf
// Grid (S/128, B). Block 256 (8 warps x 16 rows). All operands bf16 hi/lo.
// GEMM1: A=Q[128][64] (ldmatrix), B=KeT[256][64] row-major [n][k] (ldmatrix,
//        pairs (r0,r2)/(r1,r3)). Softmax on fragments (quad shuffles).
// P stays in registers: GEMM1 C-fragments == GEMM2 A-fragments after bf16x2
// packing. GEMM2: B=Vf[256][64] = [k][n] (ldmatrix.trans, pairs (r0,r1)/(r2,r3)).
// SMEM: KeT h/l 64K | Vf h/l 64K | Q h/l 32K = 160KB.
// ---------------------------------------------------------------------------
__global__ __launch_bounds__(256) void attn_kernel(float* __restrict__ out)
{
    extern __shared__ char sm[];
    const uint32_t smb = smem_u32(sm);
    const uint32_t KEH = 0, KEL = 32768, VFH = 65536, VFL = 98304,
                   QH = 131072, QL = 147456;

    const int tid = threadIdx.x, lane = tid & 31, warp = tid >> 5;
    const int b = blockIdx.y;
    const int s0 = blockIdx.x * 128;
    const int g = lane >> 2, q = lane & 3;
    const int lr = lane & 15, lcb = (lane >> 4) * 16;

    // ---- load all tiles via cp.async ----
    {
        const __nv_bfloat16* keh = g_Keh + (size_t)b * KCC * DD;
        const __nv_bfloat16* kel = g_Kel + (size_t)b * KCC * DD;
        const __nv_bfloat16* vfh = g_Vfh + (size_t)b * KCC * DD;
        const __nv_bfloat16* vfl = g_Vfl + (size_t)b * KCC * DD;
#pragma unroll
        for (int idx = tid; idx < 2048; idx += 256) {
            int row = idx >> 3, seg = idx & 7;
            size_t so = (size_t)row * DD + seg * 8;
            uint32_t bo = SW128((uint32_t)(row * 128 + seg * 16));
            cp16(smb + KEH + bo, keh + so);
            cp16(smb + KEL + bo, kel + so);
            cp16(smb + VFH + bo, vfh + so);
            cp16(smb + VFL + bo, vfl + so);
        }
        const __nv_bfloat16* qh = g_Qh + ((size_t)b * SS + s0) * DD;
        const __nv_bfloat16* ql = g_Ql + ((size_t)b * SS + s0) * DD;
#pragma unroll
        for (int idx = tid; idx < 1024; idx += 256) {
            int row = idx >> 3, seg = idx & 7;
            size_t so = (size_t)row * DD + seg * 8;
            uint32_t bo = SW128((uint32_t)(row * 128 + seg * 16));
            cp16(smb + QH + bo, qh + so);
            cp16(smb + QL + bo, ql + so);
        }
        cp_commit();
        cp_wait<0>();
        __syncthreads();
    }

    // ---- GEMM1: acc[nf][4], nf = kc/8 (0..31); warp rows = warp*16 ----
    float acc[32][4];
#pragma unroll
    for (int nf = 0; nf < 32; nf++)
#pragma unroll
        for (int i = 0; i < 4; i++) acc[nf][i] = 0.f;

#pragma unroll
    for (int kk = 0; kk < 4; kk++) {
        uint32_t qh[4], ql[4];
        uint32_t offA = SW128((uint32_t)((warp * 16 + lr) * 128 + kk * 32 + lcb));
        ldm_x4(qh, smb + QH + offA);
        ldm_x4(ql, smb + QL + offA);
#pragma unroll
        for (int j = 0; j < 16; j++) {
            uint32_t off = SW128((uint32_t)((j * 16 + lr) * 128 + kk * 32 + lcb));
            uint32_t bh[4], bl[4];
            ldm_x4(bh, smb + KEH + off);
            ldm_x4(bl, smb + KEL + off);
            mma_bf16(acc[2 * j],     qh, bh[0], bh[2]);
            mma_bf16(acc[2 * j],     ql, bh[0], bh[2]);
            mma_bf16(acc[2 * j],     qh, bl[0], bl[2]);
            mma_bf16(acc[2 * j + 1], qh, bh[1], bh[3]);
            mma_bf16(acc[2 * j + 1], ql, bh[1], bh[3]);
            mma_bf16(acc[2 * j + 1], qh, bl[1], bl[3]);
        }
    }

    // ---- mask + softmax on fragments (rows rowa = .. + g, rowb = +8) ----
    const int rowa = s0 + warp * 16 + g;
    const int rowb = rowa + 8;
    float mxa = -3.4e38f, mxb = -3.4e38f;
#pragma unroll
    for (int nf = 0; nf < 32; nf++) {
        const int kc = 8 * nf + 2 * q;
        acc[nf][0] = (kc     >= rowa) ? acc[nf][0] * 0.125f : -1e10f;
        acc[nf][1] = (kc + 1 >= rowa) ? acc[nf][1] * 0.125f : -1e10f;
        acc[nf][2] = (kc     >= rowb) ? acc[nf][2] * 0.125f : -1e10f;
        acc[nf][3] = (kc + 1 >= rowb) ? acc[nf][3] * 0.125f : -1e10f;
        mxa = fmaxf(mxa, fmaxf(acc[nf][0], acc[nf][1]));
        mxb = fmaxf(mxb, fmaxf(acc[nf][2], acc[nf][3]));
    }
#pragma unroll
    for (int o = 1; o <= 2; o <<= 1) {
        mxa = fmaxf(mxa, __shfl_xor_sync(0xffffffffu, mxa, o));
        mxb = fmaxf(mxb, __shfl_xor_sync(0xffffffffu, mxb, o));
    }
    float sa = 0.f, sb = 0.f;
#pragma unroll
    for (int nf = 0; nf < 32; nf++) {
        acc[nf][0] = __expf(acc[nf][0] - mxa);
        acc[nf][1] = __expf(acc[nf][1] - mxa);
        acc[nf][2] = __expf(acc[nf][2] - mxb);
        acc[nf][3] = __expf(acc[nf][3] - mxb);
        sa += acc[nf][0] + acc[nf][1];
        sb += acc[nf][2] + acc[nf][3];
    }
#pragma unroll
    for (int o = 1; o <= 2; o <<= 1) {
        sa += __shfl_xor_sync(0xffffffffu, sa, o);
        sb += __shfl_xor_sync(0xffffffffu, sb, o);
    }
    const float inva = 1.f / sa, invb = 1.f / sb;

    // ---- convert P fragments -> bf16x2 hi/lo (A-fragments for GEMM2) ----
    uint32_t pAh[32], pAl[32], pBh[32], pBl[32];
#pragma unroll
    for (int nf = 0; nf < 32; nf++) {
        float p0 = acc[nf][0] * inva, p1 = acc[nf][1] * inva;
        float p2 = acc[nf][2] * invb, p3 = acc[nf][3] * invb;
        pAh[nf] = packbf(p0, p1);
        pBh[nf] = packbf(p2, p3);
        float r0 = p0 - __bfloat162float(__float2bfloat16(p0));
        float r1 = p1 - __bfloat162float(__float2bfloat16(p1));
        float r2 = p2 - __bfloat162float(__float2bfloat16(p2));
        float r3 = p3 - __bfloat162float(__float2bfloat16(p3));
        pAl[nf] = packbf(r0, r1);
        pBl[nf] = packbf(r2, r3);
    }

    // ---- GEMM2: out(16x64) = P(16x256) @ Vf(256x64) ----
    float acc2[8][4];
#pragma unroll
    for (int u = 0; u < 8; u++)
#pragma unroll
        for (int i = 0; i < 4; i++) acc2[u][i] = 0.f;

#pragma unroll
    for (int ks = 0; ks < 16; ks++) {
        uint32_t a_h[4] = {pAh[2 * ks], pBh[2 * ks], pAh[2 * ks + 1], pBh[2 * ks + 1]};
        uint32_t a_l[4] = {pAl[2 * ks], pBl[2 * ks], pAl[2 * ks + 1], pBl[2 * ks + 1]};
#pragma unroll
        for (int t = 0; t < 4; t++) {
            uint32_t off = SW128((uint32_t)((ks * 16 + lr) * 128 + t * 32 + lcb));
            uint32_t vh[4], vl[4];
            ldm_x4_t(vh, smb + VFH + off);
            ldm_x4_t(vl, smb + VFL + off);
            mma_bf16(acc2[2 * t],     a_h, vh[0], vh[1]);
            mma_bf16(acc2[2 * t],     a_l, vh[0], vh[1]);
            mma_bf16(acc2[2 * t],     a_h, vl[0], vl[1]);
            mma_bf16(acc2[2 * t + 1], a_h, vh[2], vh[3]);
            mma_bf16(acc2[2 * t + 1], a_l, vh[2], vh[3]);
            mma_bf16(acc2[2 * t + 1], a_h, vl[2], vl[3]);
        }
    }

    // ---- store ----
    float* ob = out + (size_t)b * SS * DD;
#pragma unroll
    for (int u = 0; u < 8; u++) {
        const int d0 = 8 * u + 2 * q;
        *reinterpret_cast<float2*>(&ob[(size_t)rowa * DD + d0]) =
            make_float2(acc2[u][0], acc2[u][1]);
        *reinterpret_cast<float2*>(&ob[(size_t)rowb * DD + d0]) =
            make_float2(acc2[u][2], acc2[u][3]);
    }
}

// ---------------------------------------------------------------------------
// Harness entry. Inputs: Q, K, V, E_w, E_b, F_w, F_b. Output f32 [B,S,D].
// ---------------------------------------------------------------------------
extern "C" void kernel_launch(void* const* d_in, const int* in_sizes, int n_in,
                              void* d_out, int out_size)
{
    (void)in_sizes; (void)n_in; (void)out_size;
    const float* Q   = (const float*)d_in[0];
    const float* K   = (const float*)d_in[1];
    const float* V   = (const float*)d_in[2];
    const float* E_w = (const float*)d_in[3];
    const float* E_b = (const float*)d_in[4];
    const float* F_w = (const float*)d_in[5];
    const float* F_b = (const float*)d_in[6];
    float* out = (float*)d_out;

    const int proj_smem = 2 * 49152;   // 96 KB
    const int attn_smem = 163840;      // 160 KB
    cudaFuncSetAttribute(proj_mma_kernel,
                         cudaFuncAttributeMaxDynamicSharedMemorySize, proj_smem);
    cudaFuncSetAttribute(attn_kernel,
                         cudaFuncAttributeMaxDynamicSharedMemorySize, attn_smem);

    conv_w_kernel<<<dim3(1024, 2), 256>>>(E_w, F_w);
    conv_qkv_kernel<<<dim3(8192, 3), 256>>>(Q, K, V);
    proj_mma_kernel<<<dim3(2, BB, 2), 256, proj_smem>>>(E_b, F_b);
    attn_kernel<<<dim3(SS / 128, BB), 256, attn_smem>>>(out);
}

// round 6
// speedup vs baseline: 6.0402x; 1.5162x over previous
#include <cuda_runtime.h>
#include <cuda_bf16.h>
#include <cstdint>

#define BB 32
#define SS 4096
#define DD 64
#define KCC 256

// ------------------------- device global scratch ---------------------------
__device__ __nv_bfloat16 g_Wh[2 * KCC * SS];       // [proj][kc][s] hi
__device__ __nv_bfloat16 g_Wl[2 * KCC * SS];       // lo
__device__ __nv_bfloat16 g_Xh[2 * BB * SS * DD];   // [K/V][b][s][d] hi
__device__ __nv_bfloat16 g_Xl[2 * BB * SS * DD];   // lo
__device__ __nv_bfloat16 g_Keh[BB * KCC * DD];     // [b][kc][d] hi  (= Ke^T)
__device__ __nv_bfloat16 g_Kel[BB * KCC * DD];     // lo
__device__ __nv_bfloat16 g_Vfh[BB * KCC * DD];     // [b][kc][d] hi
__device__ __nv_bfloat16 g_Vfl[BB * KCC * DD];     // lo

// ------------------------------ helpers ------------------------------------
__device__ __forceinline__ uint32_t smem_u32(const void* p) {
    uint32_t a;
    asm("{ .reg .u64 t; cvta.to.shared.u64 t, %1; cvt.u32.u64 %0, t; }"
        : "=r"(a) : "l"(p));
    return a;
}
#define SW128(x) ((x) ^ (((x) >> 3) & 0x70))

__device__ __forceinline__ void cp16(uint32_t dst, const void* src) {
    asm volatile("cp.async.cg.shared.global [%0], [%1], 16;"
                 :: "r"(dst), "l"(src) : "memory");
}
__device__ __forceinline__ void cp_commit() {
    asm volatile("cp.async.commit_group;" ::: "memory");
}
template <int N>
__device__ __forceinline__ void cp_wait() {
    asm volatile("cp.async.wait_group %0;" :: "n"(N) : "memory");
}
__device__ __forceinline__ void ldm_x4(uint32_t* r, uint32_t addr) {
    asm volatile("ldmatrix.sync.aligned.m8n8.x4.shared.b16 {%0,%1,%2,%3}, [%4];"
                 : "=r"(r[0]), "=r"(r[1]), "=r"(r[2]), "=r"(r[3]) : "r"(addr));
}
__device__ __forceinline__ void ldm_x4_t(uint32_t* r, uint32_t addr) {
    asm volatile("ldmatrix.sync.aligned.m8n8.x4.trans.shared.b16 {%0,%1,%2,%3}, [%4];"
                 : "=r"(r[0]), "=r"(r[1]), "=r"(r[2]), "=r"(r[3]) : "r"(addr));
}
__device__ __forceinline__ void mma_bf16(
    float* c, const uint32_t* a, uint32_t b0, uint32_t b1) {
    asm volatile(
        "mma.sync.aligned.m16n8k16.row.col.f32.bf16.bf16.f32 "
        "{%0,%1,%2,%3}, {%4,%5,%6,%7}, {%8,%9}, {%0,%1,%2,%3};"
        : "+f"(c[0]), "+f"(c[1]), "+f"(c[2]), "+f"(c[3])
        : "r"(a[0]), "r"(a[1]), "r"(a[2]), "r"(a[3]), "r"(b0), "r"(b1));
}
__device__ __forceinline__ uint32_t packbf(float lo, float hi) {
    uint32_t r;
    asm("cvt.rn.bf16x2.f32 %0, %1, %2;" : "=r"(r) : "f"(hi), "f"(lo));
    return r;
}

// ---------------------------------------------------------------------------
// conv_w: E_w / F_w (fp32 [256][4096]) -> bf16 hi/lo, same layout.
// ---------------------------------------------------------------------------
__global__ __launch_bounds__(256) void conv_w_kernel(
    const float* __restrict__ Ew, const float* __restrict__ Fw)
{
    const int y = blockIdx.y;
    const float4* src = reinterpret_cast<const float4*>(y ? Fw : Ew);
    const int i = blockIdx.x * 256 + threadIdx.x;
    float4 v = src[i];
    __nv_bfloat16 h0 = __float2bfloat16(v.x), h1 = __float2bfloat16(v.y),
                  h2 = __float2bfloat16(v.z), h3 = __float2bfloat16(v.w);
    __nv_bfloat16 l0 = __float2bfloat16(v.x - __bfloat162float(h0));
    __nv_bfloat16 l1 = __float2bfloat16(v.y - __bfloat162float(h1));
    __nv_bfloat16 l2 = __float2bfloat16(v.z - __bfloat162float(h2));
    __nv_bfloat16 l3 = __float2bfloat16(v.w - __bfloat162float(h3));
    __nv_bfloat162* oh = reinterpret_cast<__nv_bfloat162*>(
        g_Wh + (size_t)y * KCC * SS) + 2 * i;
    __nv_bfloat162* ol = reinterpret_cast<__nv_bfloat162*>(
        g_Wl + (size_t)y * KCC * SS) + 2 * i;
    oh[0] = __halves2bfloat162(h0, h1);
    oh[1] = __halves2bfloat162(h2, h3);
    ol[0] = __halves2bfloat162(l0, l1);
    ol[1] = __halves2bfloat162(l2, l3);
}

// ---------------------------------------------------------------------------
// conv_kv: K / V (fp32 [b][s][d]) -> bf16 hi/lo, same layout.  Grid (8192, 2).
// ---------------------------------------------------------------------------
__global__ __launch_bounds__(256) void conv_kv_kernel(
    const float* __restrict__ K, const float* __restrict__ V)
{
    const int z = blockIdx.y;
    const float4* src = reinterpret_cast<const float4*>(z ? V : K);
    const size_t i = (size_t)blockIdx.x * 256 + threadIdx.x;
    float4 v = src[i];
    __nv_bfloat16 h0 = __float2bfloat16(v.x), h1 = __float2bfloat16(v.y),
                  h2 = __float2bfloat16(v.z), h3 = __float2bfloat16(v.w);
    __nv_bfloat16 l0 = __float2bfloat16(v.x - __bfloat162float(h0));
    __nv_bfloat16 l1 = __float2bfloat16(v.y - __bfloat162float(h1));
    __nv_bfloat16 l2 = __float2bfloat16(v.z - __bfloat162float(h2));
    __nv_bfloat16 l3 = __float2bfloat16(v.w - __bfloat162float(h3));
    __nv_bfloat162* oh = reinterpret_cast<__nv_bfloat162*>(
        g_Xh + (size_t)z * BB * SS * DD) + 2 * i;
    __nv_bfloat162* ol = reinterpret_cast<__nv_bfloat162*>(
        g_Xl + (size_t)z * BB * SS * DD) + 2 * i;
    oh[0] = __halves2bfloat162(h0, h1);
    oh[1] = __halves2bfloat162(h2, h3);
    ol[0] = __halves2bfloat162(l0, l1);
    ol[1] = __halves2bfloat162(l2, l3);
}

// ---------------------------------------------------------------------------
// proj_mma: mma.sync bf16 3-split GEMM, 4-stage cp.async pipeline.
//   D[kc][d] = sum_s W[kc][s] * X[s][d]   (M=128 kc, N=64 d, K=4096 s)
// Grid (2, B, 2). Block 256 (2 m-groups x 4 n-groups; warp tile 64x16).
// SMEM: 4 stages x 48KB = 192KB.
// ---------------------------------------------------------------------------
__global__ __launch_bounds__(256) void proj_mma_kernel(
    const float* __restrict__ E_b, const float* __restrict__ F_b)
{
    extern __shared__ char sm[];
    const uint32_t smb = smem_u32(sm);
    const int tid = threadIdx.x, wid = tid >> 5, lane = tid & 31;
    const int kc0 = blockIdx.x * 128, b = blockIdx.y, proj = blockIdx.z;
    const int mw = wid >> 2, nw = wid & 3;
    const int g = lane >> 2, q = lane & 3;

    const __nv_bfloat16* Wh = g_Wh + ((size_t)proj * KCC + kc0) * SS;
    const __nv_bfloat16* Wl = g_Wl + ((size_t)proj * KCC + kc0) * SS;
    const __nv_bfloat16* Xh = g_Xh + ((size_t)proj * BB + b) * SS * DD;
    const __nv_bfloat16* Xl = g_Xl + ((size_t)proj * BB + b) * SS * DD;

    float acc[4][2][4];
#pragma unroll
    for (int mf = 0; mf < 4; mf++)
#pragma unroll
        for (int nf = 0; nf < 2; nf++)
#pragma unroll
            for (int i = 0; i < 4; i++) acc[mf][nf][i] = 0.f;

    const int NC = SS / 64;   // 64 chunks

    auto load_chunk = [&](int c) {
        const uint32_t buf = smb + (c & 3) * 49152;
#pragma unroll
        for (int idx = tid; idx < 1024; idx += 256) {
            int row = idx >> 3, s16 = idx & 7;
            size_t so = (size_t)row * SS + c * 64 + s16 * 8;
            uint32_t bo = SW128((uint32_t)(row * 128 + s16 * 16));
            cp16(buf + bo,         Wh + so);
            cp16(buf + 16384 + bo, Wl + so);
        }
#pragma unroll
        for (int idx = tid; idx < 512; idx += 256) {
            int row = idx >> 3, s16 = idx & 7;
            size_t so = (size_t)(c * 64 + row) * DD + s16 * 8;
            uint32_t bo = SW128((uint32_t)(row * 128 + s16 * 16));
            cp16(buf + 32768 + bo, Xh + so);
            cp16(buf + 40960 + bo, Xl + so);
        }
        cp_commit();
    };

    load_chunk(0);
    load_chunk(1);
    load_chunk(2);

    for (int c = 0; c < NC; c++) {
        if (c + 3 < NC) { load_chunk(c + 3); cp_wait<3>(); }
        else            { cp_wait<0>(); }
        __syncthreads();

        const uint32_t buf = smb + (c & 3) * 49152;
        const uint32_t Ah = buf, Al = buf + 16384;
        const uint32_t Bh = buf + 32768, Bl = buf + 40960;
        const int lr = lane & 15, lc = (lane >> 4) * 16;

#pragma unroll
        for (int kk = 0; kk < 4; kk++) {
            uint32_t bh[4], bl[4];
            {
                uint32_t off = SW128((uint32_t)(
                    (kk * 16 + lr) * 128 + nw * 32 + lc));
                ldm_x4_t(bh, Bh + off);
                ldm_x4_t(bl, Bl + off);
            }
#pragma unroll
            for (int mf = 0; mf < 4; mf++) {
                uint32_t ah[4], al[4];
                uint32_t off = SW128((uint32_t)(
                    (mw * 64 + mf * 16 + lr) * 128 + kk * 32 + lc));
                ldm_x4(ah, Ah + off);
                ldm_x4(al, Al + off);
#pragma unroll
                for (int nf = 0; nf < 2; nf++) {
                    mma_bf16(acc[mf][nf], ah, bh[2 * nf], bh[2 * nf + 1]);
                    mma_bf16(acc[mf][nf], al, bh[2 * nf], bh[2 * nf + 1]);
                    mma_bf16(acc[mf][nf], ah, bl[2 * nf], bl[2 * nf + 1]);
                }
            }
        }
        __syncthreads();
    }

    // ---- epilogue: bias add, bf16 hi/lo split, store [b][kc][d] ----
    const float* bias = proj ? F_b : E_b;
    __nv_bfloat16* oh = (proj ? g_Vfh : g_Keh) + ((size_t)b * KCC + kc0) * DD;
    __nv_bfloat16* ol = (proj ? g_Vfl : g_Kel) + ((size_t)b * KCC + kc0) * DD;
#pragma unroll
    for (int mf = 0; mf < 4; mf++) {
        const int kcl = mw * 64 + mf * 16 + g;
        const float bv0 = bias[kc0 + kcl];
        const float bv8 = bias[kc0 + kcl + 8];
#pragma unroll
        for (int nf = 0; nf < 2; nf++) {
            const int d0 = nw * 16 + nf * 8 + 2 * q;
            float v0 = acc[mf][nf][0] + bv0, v1 = acc[mf][nf][1] + bv0;
            float v2 = acc[mf][nf][2] + bv8, v3 = acc[mf][nf][3] + bv8;
            float r0 = v0 - __bfloat162float(__float2bfloat16(v0));
            float r1 = v1 - __bfloat162float(__float2bfloat16(v1));
            float r2 = v2 - __bfloat162float(__float2bfloat16(v2));
            float r3 = v3 - __bfloat162float(__float2bfloat16(v3));
            *reinterpret_cast<uint32_t*>(&oh[(size_t)kcl * DD + d0]) = packbf(v0, v1);
            *reinterpret_cast<uint32_t*>(&oh[(size_t)(kcl + 8) * DD + d0]) = packbf(v2, v3);
            *reinterpret_cast<uint32_t*>(&ol[(size_t)kcl * DD + d0]) = packbf(r0, r1);
            *reinterpret_cast<uint32_t*>(&ol[(size_t)(kcl + 8) * DD + d0]) = packbf(r2, r3);
        }
    }
}

// ---------------------------------------------------------------------------
// attn: tensor-core fused attention, ONLY rows 0..255 per batch (rows >= KC
// are fully causally masked -> handled by bcast_kernel).
// Grid (2, B). Block 256 (8 warps x 16 rows). Causal tile-skip: kc-tile j is
// all-zero (exactly) when 16j+15 < warp's min row -> skip its MMAs.
// Q converted fp32 -> bf16 hi/lo in-kernel.
// ---------------------------------------------------------------------------
__global__ __launch_bounds__(256) void attn_kernel(
    const float* __restrict__ Qf, float* __restrict__ out)
{
    extern __shared__ char sm[];
    const uint32_t smb = smem_u32(sm);
    const uint32_t KEH = 0, KEL = 32768, VFH = 65536, VFL = 98304,
                   QH = 131072, QL = 147456;

    const int tid = threadIdx.x, lane = tid & 31, warp = tid >> 5;
    const int b = blockIdx.y;
    const int s0 = blockIdx.x * 128;
    const int g = lane >> 2, q = lane & 3;
    const int lr = lane & 15, lcb = (lane >> 4) * 16;

    // ---- Ke / Vf tiles via cp.async ----
    {
        const __nv_bfloat16* keh = g_Keh + (size_t)b * KCC * DD;
        const __nv_bfloat16* kel = g_Kel + (size_t)b * KCC * DD;
        const __nv_bfloat16* vfh = g_Vfh + (size_t)b * KCC * DD;
        const __nv_bfloat16* vfl = g_Vfl + (size_t)b * KCC * DD;
#pragma unroll
        for (int idx = tid; idx < 2048; idx += 256) {
            int row = idx >> 3, seg = idx & 7;
            size_t so = (size_t)row * DD + seg * 8;
            uint32_t bo = SW128((uint32_t)(row * 128 + seg * 16));
            cp16(smb + KEH + bo, keh + so);
            cp16(smb + KEL + bo, kel + so);
            cp16(smb + VFH + bo, vfh + so);
            cp16(smb + VFL + bo, vfl + so);
        }
        cp_commit();
    }
    // ---- Q: load fp32, split to bf16 hi/lo in smem ----
    {
        const float* qb = Qf + ((size_t)b * SS + s0) * DD;
#pragma unroll
        for (int idx = tid; idx < 1024; idx += 256) {
            int row = idx >> 3, seg = idx & 7;
            const float* qp = qb + (size_t)row * DD + seg * 8;
            float4 v0 = *reinterpret_cast<const float4*>(qp);
            float4 v1 = *reinterpret_cast<const float4*>(qp + 4);
            uint32_t bo = SW128((uint32_t)(row * 128 + seg * 16));
            uint4 h, l;
            h.x = packbf(v0.x, v0.y); h.y = packbf(v0.z, v0.w);
            h.z = packbf(v1.x, v1.y); h.w = packbf(v1.z, v1.w);
            l.x = packbf(v0.x - __bfloat162float(__float2bfloat16(v0.x)),
                         v0.y - __bfloat162float(__float2bfloat16(v0.y)));
            l.y = packbf(v0.z - __bfloat162float(__float2bfloat16(v0.z)),
                         v0.w - __bfloat162float(__float2bfloat16(v0.w)));
            l.z = packbf(v1.x - __bfloat162float(__float2bfloat16(v1.x)),
                         v1.y - __bfloat162float(__float2bfloat16(v1.y)));
            l.w = packbf(v1.z - __bfloat162float(__float2bfloat16(v1.z)),
                         v1.w - __bfloat162float(__float2bfloat16(v1.w)));
            *reinterpret_cast<uint4*>(sm + QH + bo) = h;
            *reinterpret_cast<uint4*>(sm + QL + bo) = l;
        }
        cp_wait<0>();
        __syncthreads();
    }

    // min row of this warp -> first possibly-unmasked kc tile
    const int j0 = blockIdx.x * 8 + warp;

    // ---- GEMM1: acc[nf][4], nf = kc/8 ----
    float acc[32][4];
#pragma unroll
    for (int nf = 0; nf < 32; nf++)
#pragma unroll
        for (int i = 0; i < 4; i++) acc[nf][i] = 0.f;

#pragma unroll
    for (int kk = 0; kk < 4; kk++) {
        uint32_t qh[4], ql[4];
        uint32_t offA = SW128((uint32_t)((warp * 16 + lr) * 128 + kk * 32 + lcb));
        ldm_x4(qh, smb + QH + offA);
        ldm_x4(ql, smb + QL + offA);
#pragma unroll
        for (int j = 0; j < 16; j++) {
            if (j >= j0) {     // warp-uniform causal tile skip
                uint32_t off = SW128((uint32_t)((j * 16 + lr) * 128 + kk * 32 + lcb));
                uint32_t bh[4], bl[4];
                ldm_x4(bh, smb + KEH + off);
                ldm_x4(bl, smb + KEL + off);
                mma_bf16(acc[2 * j],     qh, bh[0], bh[2]);
                mma_bf16(acc[2 * j],     ql, bh[0], bh[2]);
                mma_bf16(acc[2 * j],     qh, bl[0], bl[2]);
                mma_bf16(acc[2 * j + 1], qh, bh[1], bh[3]);
                mma_bf16(acc[2 * j + 1], ql, bh[1], bh[3]);
                mma_bf16(acc[2 * j + 1], qh, bl[1], bl[3]);
            }
        }
    }

    // ---- mask + softmax on fragments ----
    const int rowa = s0 + warp * 16 + g;
    const int rowb = rowa + 8;
    float mxa = -3.4e38f, mxb = -3.4e38f;
#pragma unroll
    for (int nf = 0; nf < 32; nf++) {
        const int kc = 8 * nf + 2 * q;
        acc[nf][0] = (kc     >= rowa) ? acc[nf][0] * 0.125f : -1e10f;
        acc[nf][1] = (kc + 1 >= rowa) ? acc[nf][1] * 0.125f : -1e10f;
        acc[nf][2] = (kc     >= rowb) ? acc[nf][2] * 0.125f : -1e10f;
        acc[nf][3] = (kc + 1 >= rowb) ? acc[nf][3] * 0.125f : -1e10f;
        mxa = fmaxf(mxa, fmaxf(acc[nf][0], acc[nf][1]));
        mxb = fmaxf(mxb, fmaxf(acc[nf][2], acc[nf][3]));
    }
#pragma unroll
    for (int o = 1; o <= 2; o <<= 1) {
        mxa = fmaxf(mxa, __shfl_xor_sync(0xffffffffu, mxa, o));
        mxb = fmaxf(mxb, __shfl_xor_sync(0xffffffffu, mxb, o));
    }
    float sa = 0.f, sb = 0.f;
#pragma unroll
    for (int nf = 0; nf < 32; nf++) {
        acc[nf][0] = __expf(acc[nf][0] - mxa);
        acc[nf][1] = __expf(acc[nf][1] - mxa);
        acc[nf][2] = __expf(acc[nf][2] - mxb);
        acc[nf][3] = __expf(acc[nf][3] - mxb);
        sa += acc[nf][0] + acc[nf][1];
        sb += acc[nf][2] + acc[nf][3];
    }
#pragma unroll
    for (int o = 1; o <= 2; o <<= 1) {
        sa += __shfl_xor_sync(0xffffffffu, sa, o);
        sb += __shfl_xor_sync(0xffffffffu, sb, o);
    }
    const float inva = 1.f / sa, invb = 1.f / sb;

    // ---- P fragments -> bf16x2 hi/lo (A-fragments for GEMM2) ----
    uint32_t pAh[32], pAl[32], pBh[32], pBl[32];
#pragma unroll
    for (int nf = 0; nf < 32; nf++) {
        float p0 = acc[nf][0] * inva, p1 = acc[nf][1] * inva;
        float p2 = acc[nf][2] * invb, p3 = acc[nf][3] * invb;
        pAh[nf] = packbf(p0, p1);
        pBh[nf] = packbf(p2, p3);
        pAl[nf] = packbf(p0 - __bfloat162float(__float2bfloat16(p0)),
                         p1 - __bfloat162float(__float2bfloat16(p1)));
        pBl[nf] = packbf(p2 - __bfloat162float(__float2bfloat16(p2)),
                         p3 - __bfloat162float(__float2bfloat16(p3)));
    }

    // ---- GEMM2: out(16x64) = P(16x256) @ Vf(256x64); skip zero P tiles ----
    float acc2[8][4];
#pragma unroll
    for (int u = 0; u < 8; u++)
#pragma unroll
        for (int i = 0; i < 4; i++) acc2[u][i] = 0.f;

#pragma unroll
    for (int ks = 0; ks < 16; ks++) {
        if (ks >= j0) {    // P is exactly zero for fully-masked kc tiles
            uint32_t a_h[4] = {pAh[2 * ks], pBh[2 * ks], pAh[2 * ks + 1], pBh[2 * ks + 1]};
            uint32_t a_l[4] = {pAl[2 * ks], pBl[2 * ks], pAl[2 * ks + 1], pBl[2 * ks + 1]};
#pragma unroll
            for (int t = 0; t < 4; t++) {
                uint32_t off = SW128((uint32_t)((ks * 16 + lr) * 128 + t * 32 + lcb));
                uint32_t vh[4], vl[4];
                ldm_x4_t(vh, smb + VFH + off);
                ldm_x4_t(vl, smb + VFL + off);
                mma_bf16(acc2[2 * t],     a_h, vh[0], vh[1]);
                mma_bf16(acc2[2 * t],     a_l, vh[0], vh[1]);
                mma_bf16(acc2[2 * t],     a_h, vl[0], vl[1]);
                mma_bf16(acc2[2 * t + 1], a_h, vh[2], vh[3]);
                mma_bf16(acc2[2 * t + 1], a_l, vh[2], vh[3]);
                mma_bf16(acc2[2 * t + 1], a_h, vl[2], vl[3]);
            }
        }
    }

    // ---- store ----
    float* ob = out + (size_t)b * SS * DD;
#pragma unroll
    for (int u = 0; u < 8; u++) {
        const int d0 = 8 * u + 2 * q;
        *reinterpret_cast<float2*>(&ob[(size_t)rowa * DD + d0]) =
            make_float2(acc2[u][0], acc2[u][1]);
        *reinterpret_cast<float2*>(&ob[(size_t)rowb * DD + d0]) =
            make_float2(acc2[u][2], acc2[u][3]);
    }
}

// ---------------------------------------------------------------------------
// bcast: rows >= KC are fully masked -> P uniform (exactly 1/256) ->
//   out[b][i][:] = mean_k Vf[b][k][:]  for i in [256, 4096).
// Grid (B, 8): each block writes 480 rows. Mean recomputed per block (cheap).
// ---------------------------------------------------------------------------
__global__ __launch_bounds__(256) void bcast_kernel(float* __restrict__ out)
{
    __shared__ float psum[4][64];
    __shared__ float meanv[64];
    const int b = blockIdx.x, part = blockIdx.y;
    const int tid = threadIdx.x;

    const __nv_bfloat16* vh = g_Vfh + (size_t)b * KCC * DD;
    const __nv_bfloat16* vl = g_Vfl + (size_t)b * KCC * DD;
    const int d = tid & 63, ks = tid >> 6;
    float s = 0.f;
    for (int k = ks * 64; k < ks * 64 + 64; k++)
        s += __bfloat162float(vh[(size_t)k * DD + d]) +
             __bfloat162float(vl[(size_t)k * DD + d]);
    psum[ks][d] = s;
    __syncthreads();
    if (tid < 64)
        meanv[tid] = (psum[0][tid] + psum[1][tid] + psum[2][tid] + psum[3][tid])
                     * (1.f / 256.f);
    __syncthreads();

    const int c = tid & 15, rofs = tid >> 4;
    const float4 val = make_float4(meanv[c * 4], meanv[c * 4 + 1],
                                   meanv[c * 4 + 2], meanv[c * 4 + 3]);
    float4* ob = reinterpret_cast<float4*>(out + (size_t)b * SS * DD);
    const int r0 = KCC + part * 480;
#pragma unroll 4
    for (int r = r0 + rofs; r < r0 + 480; r += 16)
        ob[(size_t)r * 16 + c] = val;
}

// ---------------------------------------------------------------------------
// Harness entry. Inputs: Q, K, V, E_w, E_b, F_w, F_b. Output f32 [B,S,D].
// ---------------------------------------------------------------------------
extern "C" void kernel_launch(void* const* d_in, const int* in_sizes, int n_in,
                              void* d_out, int out_size)
{
    (void)in_sizes; (void)n_in; (void)out_size;
    const float* Q   = (const float*)d_in[0];
    const float* K   = (const float*)d_in[1];
    const float* V   = (const float*)d_in[2];
    const float* E_w = (const float*)d_in[3];
    const float* E_b = (const float*)d_in[4];
    const float* F_w = (const float*)d_in[5];
    const float* F_b = (const float*)d_in[6];
    float* out = (float*)d_out;

    const int proj_smem = 4 * 49152;   // 192 KB
    const int attn_smem = 163840;      // 160 KB
    cudaFuncSetAttribute(proj_mma_kernel,
                         cudaFuncAttributeMaxDynamicSharedMemorySize, proj_smem);
    cudaFuncSetAttribute(attn_kernel,
                         cudaFuncAttributeMaxDynamicSharedMemorySize, attn_smem);

    conv_w_kernel<<<dim3(1024, 2), 256>>>(E_w, F_w);
    conv_kv_kernel<<<dim3(8192, 2), 256>>>(K, V);
    proj_mma_kernel<<<dim3(2, BB, 2), 256, proj_smem>>>(E_b, F_b);
    attn_kernel<<<dim3(2, BB), 256, attn_smem>>>(Q, out);
    bcast_kernel<<<dim3(BB, 8), 256>>>(out);
}

// round 7
// speedup vs baseline: 6.5665x; 1.0871x over previous
#include <cuda_runtime.h>
#include <cuda_bf16.h>
#include <cstdint>

#define BB 32
#define SS 4096
#define DD 64
#define KCC 256

// ------------------------- device global scratch ---------------------------
__device__ __nv_bfloat16 g_Wh[2 * KCC * SS];       // [proj][kc][s] hi
__device__ __nv_bfloat16 g_Wl[2 * KCC * SS];       // lo
__device__ __nv_bfloat16 g_Keh[BB * KCC * DD];     // [b][kc][d] hi  (= Ke^T)
__device__ __nv_bfloat16 g_Kel[BB * KCC * DD];     // lo
__device__ __nv_bfloat16 g_Vfh[BB * KCC * DD];     // [b][kc][d] hi
__device__ __nv_bfloat16 g_Vfl[BB * KCC * DD];     // lo

// ------------------------------ helpers ------------------------------------
__device__ __forceinline__ uint32_t smem_u32(const void* p) {
    uint32_t a;
    asm("{ .reg .u64 t; cvta.to.shared.u64 t, %1; cvt.u32.u64 %0, t; }"
        : "=r"(a) : "l"(p));
    return a;
}
#define SW128(x) ((x) ^ (((x) >> 3) & 0x70))

__device__ __forceinline__ void cp16(uint32_t dst, const void* src) {
    asm volatile("cp.async.cg.shared.global [%0], [%1], 16;"
                 :: "r"(dst), "l"(src) : "memory");
}
__device__ __forceinline__ void cp_commit() {
    asm volatile("cp.async.commit_group;" ::: "memory");
}
template <int N>
__device__ __forceinline__ void cp_wait() {
    asm volatile("cp.async.wait_group %0;" :: "n"(N) : "memory");
}
__device__ __forceinline__ void ldm_x4(uint32_t* r, uint32_t addr) {
    asm volatile("ldmatrix.sync.aligned.m8n8.x4.shared.b16 {%0,%1,%2,%3}, [%4];"
                 : "=r"(r[0]), "=r"(r[1]), "=r"(r[2]), "=r"(r[3]) : "r"(addr));
}
__device__ __forceinline__ void ldm_x4_t(uint32_t* r, uint32_t addr) {
    asm volatile("ldmatrix.sync.aligned.m8n8.x4.trans.shared.b16 {%0,%1,%2,%3}, [%4];"
                 : "=r"(r[0]), "=r"(r[1]), "=r"(r[2]), "=r"(r[3]) : "r"(addr));
}
__device__ __forceinline__ void mma_bf16(
    float* c, const uint32_t* a, uint32_t b0, uint32_t b1) {
    asm volatile(
        "mma.sync.aligned.m16n8k16.row.col.f32.bf16.bf16.f32 "
        "{%0,%1,%2,%3}, {%4,%5,%6,%7}, {%8,%9}, {%0,%1,%2,%3};"
        : "+f"(c[0]), "+f"(c[1]), "+f"(c[2]), "+f"(c[3])
        : "r"(a[0]), "r"(a[1]), "r"(a[2]), "r"(a[3]), "r"(b0), "r"(b1));
}
__device__ __forceinline__ uint32_t packbf(float lo, float hi) {
    uint32_t r;
    asm("cvt.rn.bf16x2.f32 %0, %1, %2;" : "=r"(r) : "f"(hi), "f"(lo));
    return r;
}
__device__ __forceinline__ float bfres(float v) {   // v - bf16(v)
    return v - __bfloat162float(__float2bfloat16(v));
}

// ---------------------------------------------------------------------------
// conv_w: E_w / F_w (fp32 [256][4096]) -> bf16 hi/lo, same layout.
// ---------------------------------------------------------------------------
__global__ __launch_bounds__(256) void conv_w_kernel(
    const float* __restrict__ Ew, const float* __restrict__ Fw)
{
    const int y = blockIdx.y;
    const float4* src = reinterpret_cast<const float4*>(y ? Fw : Ew);
    const int i = blockIdx.x * 256 + threadIdx.x;
    float4 v = src[i];
    __nv_bfloat16 h0 = __float2bfloat16(v.x), h1 = __float2bfloat16(v.y),
                  h2 = __float2bfloat16(v.z), h3 = __float2bfloat16(v.w);
    __nv_bfloat16 l0 = __float2bfloat16(v.x - __bfloat162float(h0));
    __nv_bfloat16 l1 = __float2bfloat16(v.y - __bfloat162float(h1));
    __nv_bfloat16 l2 = __float2bfloat16(v.z - __bfloat162float(h2));
    __nv_bfloat16 l3 = __float2bfloat16(v.w - __bfloat162float(h3));
    __nv_bfloat162* oh = reinterpret_cast<__nv_bfloat162*>(
        g_Wh + (size_t)y * KCC * SS) + 2 * i;
    __nv_bfloat162* ol = reinterpret_cast<__nv_bfloat162*>(
        g_Wl + (size_t)y * KCC * SS) + 2 * i;
    oh[0] = __halves2bfloat162(h0, h1);
    oh[1] = __halves2bfloat162(h2, h3);
    ol[0] = __halves2bfloat162(l0, l1);
    ol[1] = __halves2bfloat162(l2, l3);
}

// ---------------------------------------------------------------------------
// proj_mma: mma.sync bf16 3-split GEMM; W via 4-stage cp.async, X (K/V fp32)
// loaded directly with register prefetch + in-kernel bf16 hi/lo conversion.
//   D[kc][d] = sum_s W[kc][s] * X[s][d]   (M=128 kc, N=64 d, K=4096 s)
// Grid (2, B, 2). Block 256.
// SMEM: W 4 x 32KB = 128KB @0 | X 2 x (8K hi + 8K lo) = 32KB @131072. 160KB.
// ---------------------------------------------------------------------------
__global__ __launch_bounds__(256) void proj_mma_kernel(
    const float* __restrict__ Kf, const float* __restrict__ Vf,
    const float* __restrict__ E_b, const float* __restrict__ F_b)
{
    extern __shared__ char sm[];
    const uint32_t smb = smem_u32(sm);
    const int tid = threadIdx.x, wid = tid >> 5, lane = tid & 31;
    const int kc0 = blockIdx.x * 128, b = blockIdx.y, proj = blockIdx.z;
    const int mw = wid >> 2, nw = wid & 3;
    const int g = lane >> 2, q = lane & 3;

    const __nv_bfloat16* Wh = g_Wh + ((size_t)proj * KCC + kc0) * SS;
    const __nv_bfloat16* Wl = g_Wl + ((size_t)proj * KCC + kc0) * SS;
    const float* Xb = (proj ? Vf : Kf) + (size_t)b * SS * DD;

    float acc[4][2][4];
#pragma unroll
    for (int mf = 0; mf < 4; mf++)
#pragma unroll
        for (int nf = 0; nf < 2; nf++)
#pragma unroll
            for (int i = 0; i < 4; i++) acc[mf][nf][i] = 0.f;

    const int NC = SS / 64;   // 64 chunks

    // W chunk loader (cp.async, one commit group per call)
    auto load_w = [&](int c) {
        const uint32_t buf = smb + (c & 3) * 32768;
#pragma unroll
        for (int idx = tid; idx < 1024; idx += 256) {
            int row = idx >> 3, s16 = idx & 7;
            size_t so = (size_t)row * SS + c * 64 + s16 * 8;
            uint32_t bo = SW128((uint32_t)(row * 128 + s16 * 16));
            cp16(buf + bo,         Wh + so);
            cp16(buf + 16384 + bo, Wl + so);
        }
        cp_commit();
    };

    // X chunk: 64 s-rows x 64 d fp32; thread owns segments tid and tid+256
    float4 xr[2][2];
    auto ldx = [&](int c) {
#pragma unroll
        for (int u = 0; u < 2; u++) {
            int seg = tid + u * 256;
            int row = seg >> 3, s16 = seg & 7;
            const float* p = Xb + (size_t)(c * 64 + row) * DD + s16 * 8;
            xr[u][0] = *reinterpret_cast<const float4*>(p);
            xr[u][1] = *reinterpret_cast<const float4*>(p + 4);
        }
    };
    auto stx = [&](int pbuf) {
        char* xbase = sm + 131072 + pbuf * 16384;
#pragma unroll
        for (int u = 0; u < 2; u++) {
            int seg = tid + u * 256;
            int row = seg >> 3, s16 = seg & 7;
            uint32_t bo = SW128((uint32_t)(row * 128 + s16 * 16));
            float4 v0 = xr[u][0], v1 = xr[u][1];
            uint4 h, l;
            h.x = packbf(v0.x, v0.y); h.y = packbf(v0.z, v0.w);
            h.z = packbf(v1.x, v1.y); h.w = packbf(v1.z, v1.w);
            l.x = packbf(bfres(v0.x), bfres(v0.y));
            l.y = packbf(bfres(v0.z), bfres(v0.w));
            l.z = packbf(bfres(v1.x), bfres(v1.y));
            l.w = packbf(bfres(v1.z), bfres(v1.w));
            *reinterpret_cast<uint4*>(xbase + bo)        = h;
            *reinterpret_cast<uint4*>(xbase + 8192 + bo) = l;
        }
    };

    load_w(0); load_w(1); load_w(2);
    ldx(0);

    for (int c = 0; c < NC; c++) {
        if (c + 3 < NC) { load_w(c + 3); cp_wait<3>(); }
        else            { cp_wait<0>(); }

        stx(c & 1);                 // convert prefetched X chunk into smem
        if (c + 1 < NC) ldx(c + 1); // prefetch next (hidden under MMA)
        __syncthreads();

        const uint32_t wbuf = smb + (c & 3) * 32768;
        const uint32_t Ah = wbuf, Al = wbuf + 16384;
        const uint32_t xb = smb + 131072 + (c & 1) * 16384;
        const uint32_t Bh = xb, Bl = xb + 8192;
        const int lr = lane & 15, lc = (lane >> 4) * 16;

#pragma unroll
        for (int kk = 0; kk < 4; kk++) {
            uint32_t bh[4], bl[4];
            {
                uint32_t off = SW128((uint32_t)(
                    (kk * 16 + lr) * 128 + nw * 32 + lc));
                ldm_x4_t(bh, Bh + off);
                ldm_x4_t(bl, Bl + off);
            }
#pragma unroll
            for (int mf = 0; mf < 4; mf++) {
                uint32_t ah[4], al[4];
                uint32_t off = SW128((uint32_t)(
                    (mw * 64 + mf * 16 + lr) * 128 + kk * 32 + lc));
                ldm_x4(ah, Ah + off);
                ldm_x4(al, Al + off);
#pragma unroll
                for (int nf = 0; nf < 2; nf++) {
                    mma_bf16(acc[mf][nf], ah, bh[2 * nf], bh[2 * nf + 1]);
                    mma_bf16(acc[mf][nf], al, bh[2 * nf], bh[2 * nf + 1]);
                    mma_bf16(acc[mf][nf], ah, bl[2 * nf], bl[2 * nf + 1]);
                }
            }
        }
        __syncthreads();
    }

    // ---- epilogue: bias add, bf16 hi/lo split, store [b][kc][d] ----
    const float* bias = proj ? F_b : E_b;
    __nv_bfloat16* oh = (proj ? g_Vfh : g_Keh) + ((size_t)b * KCC + kc0) * DD;
    __nv_bfloat16* ol = (proj ? g_Vfl : g_Kel) + ((size_t)b * KCC + kc0) * DD;
#pragma unroll
    for (int mf = 0; mf < 4; mf++) {
        const int kcl = mw * 64 + mf * 16 + g;
        const float bv0 = bias[kc0 + kcl];
        const float bv8 = bias[kc0 + kcl + 8];
#pragma unroll
        for (int nf = 0; nf < 2; nf++) {
            const int d0 = nw * 16 + nf * 8 + 2 * q;
            float v0 = acc[mf][nf][0] + bv0, v1 = acc[mf][nf][1] + bv0;
            float v2 = acc[mf][nf][2] + bv8, v3 = acc[mf][nf][3] + bv8;
            *reinterpret_cast<uint32_t*>(&oh[(size_t)kcl * DD + d0]) = packbf(v0, v1);
            *reinterpret_cast<uint32_t*>(&oh[(size_t)(kcl + 8) * DD + d0]) = packbf(v2, v3);
            *reinterpret_cast<uint32_t*>(&ol[(size_t)kcl * DD + d0]) =
                packbf(bfres(v0), bfres(v1));
            *reinterpret_cast<uint32_t*>(&ol[(size_t)(kcl + 8) * DD + d0]) =
                packbf(bfres(v2), bfres(v3));
        }
    }
}

// ---------------------------------------------------------------------------
// attn: tensor-core fused attention, rows 0..255 per batch only.
// Grid (4, B). Block 128 (4 warps x 16 rows = 64 rows/block).
// Causal tile-skip: kc-tile j all-masked (exactly zero P) when j < j0.
// SMEM: Ke h/l 64K | Vf h/l 64K | Q h/l 16K = 144KB.
// ---------------------------------------------------------------------------
__global__ __launch_bounds__(128) void attn_kernel(
    const float* __restrict__ Qf, float* __restrict__ out)
{
    extern __shared__ char sm[];
    const uint32_t smb = smem_u32(sm);
    const uint32_t KEH = 0, KEL = 32768, VFH = 65536, VFL = 98304,
                   QH = 131072, QL = 139264;

    const int tid = threadIdx.x, lane = tid & 31, warp = tid >> 5;
    const int b = blockIdx.y;
    const int s0 = blockIdx.x * 64;
    const int g = lane >> 2, q = lane & 3;
    const int lr = lane & 15, lcb = (lane >> 4) * 16;

    // ---- Ke / Vf tiles via cp.async ----
    {
        const __nv_bfloat16* keh = g_Keh + (size_t)b * KCC * DD;
        const __nv_bfloat16* kel = g_Kel + (size_t)b * KCC * DD;
        const __nv_bfloat16* vfh = g_Vfh + (size_t)b * KCC * DD;
        const __nv_bfloat16* vfl = g_Vfl + (size_t)b * KCC * DD;
#pragma unroll
        for (int idx = tid; idx < 2048; idx += 128) {
            int row = idx >> 3, seg = idx & 7;
            size_t so = (size_t)row * DD + seg * 8;
            uint32_t bo = SW128((uint32_t)(row * 128 + seg * 16));
            cp16(smb + KEH + bo, keh + so);
            cp16(smb + KEL + bo, kel + so);
            cp16(smb + VFH + bo, vfh + so);
            cp16(smb + VFL + bo, vfl + so);
        }
        cp_commit();
    }
    // ---- Q: load fp32, split to bf16 hi/lo in smem ----
    {
        const float* qb = Qf + ((size_t)b * SS + s0) * DD;
#pragma unroll
        for (int idx = tid; idx < 512; idx += 128) {
            int row = idx >> 3, seg = idx & 7;
            const float* qp = qb + (size_t)row * DD + seg * 8;
            float4 v0 = *reinterpret_cast<const float4*>(qp);
            float4 v1 = *reinterpret_cast<const float4*>(qp + 4);
            uint32_t bo = SW128((uint32_t)(row * 128 + seg * 16));
            uint4 h, l;
            h.x = packbf(v0.x, v0.y); h.y = packbf(v0.z, v0.w);
            h.z = packbf(v1.x, v1.y); h.w = packbf(v1.z, v1.w);
            l.x = packbf(bfres(v0.x), bfres(v0.y));
            l.y = packbf(bfres(v0.z), bfres(v0.w));
            l.z = packbf(bfres(v1.x), bfres(v1.y));
            l.w = packbf(bfres(v1.z), bfres(v1.w));
            *reinterpret_cast<uint4*>(sm + QH + bo) = h;
            *reinterpret_cast<uint4*>(sm + QL + bo) = l;
        }
        cp_wait<0>();
        __syncthreads();
    }

    const int j0 = blockIdx.x * 4 + warp;   // first possibly-unmasked kc tile

    // ---- GEMM1: acc[nf][4], nf = kc/8 ----
    float acc[32][4];
#pragma unroll
    for (int nf = 0; nf < 32; nf++)
#pragma unroll
        for (int i = 0; i < 4; i++) acc[nf][i] = 0.f;

#pragma unroll
    for (int kk = 0; kk < 4; kk++) {
        uint32_t qh[4], ql[4];
        uint32_t offA = SW128((uint32_t)((warp * 16 + lr) * 128 + kk * 32 + lcb));
        ldm_x4(qh, smb + QH + offA);
        ldm_x4(ql, smb + QL + offA);
#pragma unroll
        for (int j = 0; j < 16; j++) {
            if (j >= j0) {
                uint32_t off = SW128((uint32_t)((j * 16 + lr) * 128 + kk * 32 + lcb));
                uint32_t bh[4], bl[4];
                ldm_x4(bh, smb + KEH + off);
                ldm_x4(bl, smb + KEL + off);
                mma_bf16(acc[2 * j],     qh, bh[0], bh[2]);
                mma_bf16(acc[2 * j],     ql, bh[0], bh[2]);
                mma_bf16(acc[2 * j],     qh, bl[0], bl[2]);
                mma_bf16(acc[2 * j + 1], qh, bh[1], bh[3]);
                mma_bf16(acc[2 * j + 1], ql, bh[1], bh[3]);
                mma_bf16(acc[2 * j + 1], qh, bl[1], bl[3]);
            }
        }
    }

    // ---- mask + softmax on fragments ----
    const int rowa = s0 + warp * 16 + g;
    const int rowb = rowa + 8;
    float mxa = -3.4e38f, mxb = -3.4e38f;
#pragma unroll
    for (int nf = 0; nf < 32; nf++) {
        const int kc = 8 * nf + 2 * q;
        acc[nf][0] = (kc     >= rowa) ? acc[nf][0] * 0.125f : -1e10f;
        acc[nf][1] = (kc + 1 >= rowa) ? acc[nf][1] * 0.125f : -1e10f;
        acc[nf][2] = (kc     >= rowb) ? acc[nf][2] * 0.125f : -1e10f;
        acc[nf][3] = (kc + 1 >= rowb) ? acc[nf][3] * 0.125f : -1e10f;
        mxa = fmaxf(mxa, fmaxf(acc[nf][0], acc[nf][1]));
        mxb = fmaxf(mxb, fmaxf(acc[nf][2], acc[nf][3]));
    }
#pragma unroll
    for (int o = 1; o <= 2; o <<= 1) {
        mxa = fmaxf(mxa, __shfl_xor_sync(0xffffffffu, mxa, o));
        mxb = fmaxf(mxb, __shfl_xor_sync(0xffffffffu, mxb, o));
    }
    float sa = 0.f, sb = 0.f;
#pragma unroll
    for (int nf = 0; nf < 32; nf++) {
        acc[nf][0] = __expf(acc[nf][0] - mxa);
        acc[nf][1] = __expf(acc[nf][1] - mxa);
        acc[nf][2] = __expf(acc[nf][2] - mxb);
        acc[nf][3] = __expf(acc[nf][3] - mxb);
        sa += acc[nf][0] + acc[nf][1];
        sb += acc[nf][2] + acc[nf][3];
    }
#pragma unroll
    for (int o = 1; o <= 2; o <<= 1) {
        sa += __shfl_xor_sync(0xffffffffu, sa, o);
        sb += __shfl_xor_sync(0xffffffffu, sb, o);
    }
    const float inva = 1.f / sa, invb = 1.f / sb;

    // ---- P fragments -> bf16x2 hi/lo (A-fragments for GEMM2) ----
    uint32_t pAh[32], pAl[32], pBh[32], pBl[32];
#pragma unroll
    for (int nf = 0; nf < 32; nf++) {
        float p0 = acc[nf][0] * inva, p1 = acc[nf][1] * inva;
        float p2 = acc[nf][2] * invb, p3 = acc[nf][3] * invb;
        pAh[nf] = packbf(p0, p1);
        pBh[nf] = packbf(p2, p3);
        pAl[nf] = packbf(bfres(p0), bfres(p1));
        pBl[nf] = packbf(bfres(p2), bfres(p3));
    }

    // ---- GEMM2: out(16x64) = P(16x256) @ Vf(256x64); skip zero P tiles ----
    float acc2[8][4];
#pragma unroll
    for (int u = 0; u < 8; u++)
#pragma unroll
        for (int i = 0; i < 4; i++) acc2[u][i] = 0.f;

#pragma unroll
    for (int ks = 0; ks < 16; ks++) {
        if (ks >= j0) {
            uint32_t a_h[4] = {pAh[2 * ks], pBh[2 * ks], pAh[2 * ks + 1], pBh[2 * ks + 1]};
            uint32_t a_l[4] = {pAl[2 * ks], pBl[2 * ks], pAl[2 * ks + 1], pBl[2 * ks + 1]};
#pragma unroll
            for (int t = 0; t < 4; t++) {
                uint32_t off = SW128((uint32_t)((ks * 16 + lr) * 128 + t * 32 + lcb));
                uint32_t vh[4], vl[4];
                ldm_x4_t(vh, smb + VFH + off);
                ldm_x4_t(vl, smb + VFL + off);
                mma_bf16(acc2[2 * t],     a_h, vh[0], vh[1]);
                mma_bf16(acc2[2 * t],     a_l, vh[0], vh[1]);
                mma_bf16(acc2[2 * t],     a_h, vl[0], vl[1]);
                mma_bf16(acc2[2 * t + 1], a_h, vh[2], vh[3]);
                mma_bf16(acc2[2 * t + 1], a_l, vh[2], vh[3]);
                mma_bf16(acc2[2 * t + 1], a_h, vl[2], vl[3]);
            }
        }
    }

    // ---- store ----
    float* ob = out + (size_t)b * SS * DD;
#pragma unroll
    for (int u = 0; u < 8; u++) {
        const int d0 = 8 * u + 2 * q;
        *reinterpret_cast<float2*>(&ob[(size_t)rowa * DD + d0]) =
            make_float2(acc2[u][0], acc2[u][1]);
        *reinterpret_cast<float2*>(&ob[(size_t)rowb * DD + d0]) =
            make_float2(acc2[u][2], acc2[u][3]);
    }
}

// ---------------------------------------------------------------------------
// bcast: rows >= KC are fully masked -> P uniform (exactly 1/256) ->
//   out[b][i][:] = mean_k Vf[b][k][:]  for i in [256, 4096).
// Grid (B, 16): each block writes 240 rows.
// ---------------------------------------------------------------------------
__global__ __launch_bounds__(256) void bcast_kernel(float* __restrict__ out)
{
    __shared__ float psum[4][64];
    __shared__ float meanv[64];
    const int b = blockIdx.x, part = blockIdx.y;
    const int tid = threadIdx.x;

    const __nv_bfloat16* vh = g_Vfh + (size_t)b * KCC * DD;
    const __nv_bfloat16* vl = g_Vfl + (size_t)b * KCC * DD;
    const int d = tid & 63, ks = tid >> 6;
    float s = 0.f;
    for (int k = ks * 64; k < ks * 64 + 64; k++)
        s += __bfloat162float(vh[(size_t)k * DD + d]) +
             __bfloat162float(vl[(size_t)k * DD + d]);
    psum[ks][d] = s;
    __syncthreads();
    if (tid < 64)
        meanv[tid] = (psum[0][tid] + psum[1][tid] + psum[2][tid] + psum[3][tid])
                     * (1.f / 256.f);
    __syncthreads();

    const int c = tid & 15, rofs = tid >> 4;
    const float4 val = make_float4(meanv[c * 4], meanv[c * 4 + 1],
                                   meanv[c * 4 + 2], meanv[c * 4 + 3]);
    float4* ob = reinterpret_cast<float4*>(out + (size_t)b * SS * DD);
    const int r0 = KCC + part * 240;
#pragma unroll 5
    for (int r = r0 + rofs; r < r0 + 240; r += 16)
        ob[(size_t)r * 16 + c] = val;
}

// ---------------------------------------------------------------------------
// Harness entry. Inputs: Q, K, V, E_w, E_b, F_w, F_b. Output f32 [B,S,D].
// ---------------------------------------------------------------------------
extern "C" void kernel_launch(void* const* d_in, const int* in_sizes, int n_in,
                              void* d_out, int out_size)
{
    (void)in_sizes; (void)n_in; (void)out_size;
    const float* Q   = (const float*)d_in[0];
    const float* K   = (const float*)d_in[1];
    const float* V   = (const float*)d_in[2];
    const float* E_w = (const float*)d_in[3];
    const float* E_b = (const float*)d_in[4];
    const float* F_w = (const float*)d_in[5];
    const float* F_b = (const float*)d_in[6];
    float* out = (float*)d_out;

    const int proj_smem = 163840;   // 160 KB
    const int attn_smem = 147456;   // 144 KB
    cudaFuncSetAttribute(proj_mma_kernel,
                         cudaFuncAttributeMaxDynamicSharedMemorySize, proj_smem);
    cudaFuncSetAttribute(attn_kernel,
                         cudaFuncAttributeMaxDynamicSharedMemorySize, attn_smem);

    conv_w_kernel<<<dim3(1024, 2), 256>>>(E_w, F_w);
    proj_mma_kernel<<<dim3(2, BB, 2), 256, proj_smem>>>(K, V, E_b, F_b);
    attn_kernel<<<dim3(4, BB), 128, attn_smem>>>(Q, out);
    bcast_kernel<<<dim3(BB, 16), 256>>>(out);
}